// round 13
// baseline (speedup 1.0000x reference)
#include <cuda_runtime.h>
#include <cuda_fp16.h>
#include <cstdint>

#define B_ 4
#define L_ 1024
#define H_ 8
#define PLANE (1024*1024)

// fp16 scratch planes (64 MB each, zero-initialized .bss). Never-written
// regions (strictly-above-diagonal tiles) stay 0x0000 = +0.0h deterministically.
__device__ __half g_h1[(size_t)B_*H_*L_*L_];   // S1, then A2
__device__ __half g_h2[(size_t)B_*H_*L_*L_];   // E = exp(S2)
__device__ float  g_part[(size_t)B_*H_*L_*32];
__device__ float  g_invz[(size_t)B_*H_*L_];

__device__ __forceinline__ void mma_f16(float c[4],
                                        uint32_t a0, uint32_t a1, uint32_t a2, uint32_t a3,
                                        uint32_t b0, uint32_t b1) {
    asm volatile(
        "mma.sync.aligned.m16n8k16.row.col.f32.f16.f16.f32 "
        "{%0,%1,%2,%3}, {%4,%5,%6,%7}, {%8,%9}, {%0,%1,%2,%3};"
        : "+f"(c[0]), "+f"(c[1]), "+f"(c[2]), "+f"(c[3])
        : "r"(a0), "r"(a1), "r"(a2), "r"(a3), "r"(b0), "r"(b1));
}

__device__ __forceinline__ float4 ldh4(const __half* p) {
    uint2 u = *(const uint2*)p;
    __half2 h0 = *(__half2*)&u.x;
    __half2 h1 = *(__half2*)&u.y;
    float2 f0 = __half22float2(h0);
    float2 f1 = __half22float2(h1);
    return make_float4(f0.x, f0.y, f1.x, f1.y);
}

__device__ __forceinline__ void sth4(__half* p, float4 v) {
    __half2 a = __floats2half2_rn(v.x, v.y);
    __half2 b = __floats2half2_rn(v.z, v.w);
    uint2 u;
    u.x = *(uint32_t*)&a;
    u.y = *(uint32_t*)&b;
    *(uint2*)p = u;
}

#define BAR_SYNC_HALF(id) asm volatile("bar.sync %0, %1;" :: "r"(id), "r"(128) : "memory")

// ---------------------------------------------------------------------------
// Pass A: S1 = (Q.K^T)*scale via fp16 HMMA (fp32 accum); causal zeroed;
// masked tiles skipped. Output fp16. grid (16,16,32), block 256.
// ---------------------------------------------------------------------------
#define QK_ST 72
__global__ void __launch_bounds__(256) qk_kernel(const float* __restrict__ q,
                                                 const float* __restrict__ k)
{
    const int bh = blockIdx.z;
    const int b  = bh >> 3, h = bh & 7;
    const int l0 = blockIdx.y << 6, s0 = blockIdx.x << 6;
    if (s0 > l0 + 63) return;

    const int tid  = threadIdx.x;
    const int wrp  = tid >> 5, lane = tid & 31;
    const int gid  = lane >> 2, tg = lane & 3;
    const int m0   = (wrp & 3) << 4;
    const int n0   = (wrp >> 2) << 5;

    __shared__ __align__(16) __half Qs[64][QK_ST];
    __shared__ __align__(16) __half Ks[64][QK_ST];
    __shared__ __align__(16) float Cs[64][68];
    const float* qb = q + (size_t)b * L_ * 512 + h * 64;
    const float* kb = k + (size_t)b * L_ * 512 + h * 64;

    #pragma unroll
    for (int i = 0; i < 4; i++) {
        int row = (tid >> 4) + (i << 4);
        int c   = (tid & 15) << 2;
        sth4(&Qs[row][c], *(const float4*)&qb[(size_t)(l0 + row) * 512 + c]);
        sth4(&Ks[row][c], *(const float4*)&kb[(size_t)(s0 + row) * 512 + c]);
    }
    __syncthreads();

    float acc[4][4];
    #pragma unroll
    for (int j = 0; j < 4; j++)
        #pragma unroll
        for (int i = 0; i < 4; i++) acc[j][i] = 0.f;

    #pragma unroll
    for (int e0 = 0; e0 < 64; e0 += 16) {
        uint32_t a0 = *(const uint32_t*)&Qs[m0 + gid][e0 + 2 * tg];
        uint32_t a1 = *(const uint32_t*)&Qs[m0 + gid + 8][e0 + 2 * tg];
        uint32_t a2 = *(const uint32_t*)&Qs[m0 + gid][e0 + 2 * tg + 8];
        uint32_t a3 = *(const uint32_t*)&Qs[m0 + gid + 8][e0 + 2 * tg + 8];
        #pragma unroll
        for (int j = 0; j < 4; j++) {
            int nb = n0 + (j << 3);
            uint32_t b0 = *(const uint32_t*)&Ks[nb + gid][e0 + 2 * tg];
            uint32_t b1 = *(const uint32_t*)&Ks[nb + gid][e0 + 2 * tg + 8];
            mma_f16(acc[j], a0, a1, a2, a3, b0, b1);
        }
    }
    __syncthreads();

    #pragma unroll
    for (int j = 0; j < 4; j++) {
        int nb = n0 + (j << 3) + (tg << 1);
        Cs[m0 + gid][nb]         = acc[j][0];
        Cs[m0 + gid][nb + 1]     = acc[j][1];
        Cs[m0 + gid + 8][nb]     = acc[j][2];
        Cs[m0 + gid + 8][nb + 1] = acc[j][3];
    }
    __syncthreads();

    __half* outp = g_h1 + (size_t)bh * PLANE;
    const float scale = 0.125f;
    #pragma unroll
    for (int i = 0; i < 4; i++) {
        int row = (tid >> 4) + (i << 4);
        int c   = (tid & 15) << 2;
        int l   = l0 + row, sb = s0 + c;
        float4 v = *(const float4*)&Cs[row][c];
        float4 r;
        r.x = (sb + 0 <= l) ? v.x * scale : 0.f;
        r.y = (sb + 1 <= l) ? v.y * scale : 0.f;
        r.z = (sb + 2 <= l) ? v.z * scale : 0.f;
        r.w = (sb + 3 <= l) ? v.w * scale : 0.f;
        sth4(&outp[(size_t)l * 1024 + sb], r);
    }
}

// ---------------------------------------------------------------------------
// Pass B: S2[b,g] = sum_h wpsm[g,h]*conv3x3(S1[b,h]); writes E = exp(S2) (fp16)
// and per-row causal-masked partial sums of exp. grid (32,32,4), block 256.
// ---------------------------------------------------------------------------
__global__ void __launch_bounds__(256) convmix_kernel(const float* __restrict__ mta_k,
                                                      const float* __restrict__ wpsm)
{
    if (blockIdx.x > blockIdx.y) return;
    const int st = blockIdx.x << 5, lt = blockIdx.y << 5, b = blockIdx.z;
    const int tid = threadIdx.x;

    __shared__ __align__(16) float sm[8][34][40];
    __shared__ float kk[8][9];
    __shared__ float wm[8][8];
    if (tid < 72) kk[tid / 9][tid % 9] = mta_k[tid];
    if (tid >= 128 && tid < 192) { int t = tid - 128; wm[t >> 3][t & 7] = wpsm[t]; }

    const __half* inb = g_h1 + (size_t)b * 8 * PLANE;
    for (int idx = tid; idx < 8 * 34 * 10; idx += 256) {
        int h   = idx / 340;
        int rem = idx - h * 340;
        int r   = rem / 10;
        int c4  = rem - r * 10;
        int gl  = lt - 2 + r;
        int gs  = st - 4 + (c4 << 2);
        float4 v = make_float4(0.f, 0.f, 0.f, 0.f);
        if (gl >= 0 && gs >= 0 && gs <= 1020)
            v = ldh4(&inb[(size_t)h * PLANE + (size_t)gl * 1024 + gs]);
        *(float4*)&sm[h][r][c4 << 2] = v;
    }
    __syncthreads();

    const int li = tid >> 3;
    const int c0 = (tid & 7) << 2;
    const int l  = lt + li;
    const int sq = st + c0;

    float acc[8][4];
    #pragma unroll
    for (int g = 0; g < 8; g++)
        #pragma unroll
        for (int j = 0; j < 4; j++) acc[g][j] = 0.f;

    #pragma unroll 1
    for (int h = 0; h < 8; h++) {
        float cv0 = 0.f, cv1 = 0.f, cv2 = 0.f, cv3 = 0.f;
        #pragma unroll
        for (int i = 0; i < 3; i++) {
            const float* rp = &sm[h][li + i][c0];
            float  a  = rp[3];
            float4 m  = *(const float4*)(rp + 4);
            float2 e2 = *(const float2*)(rp + 8);
            float k0 = kk[h][i*3+0], k1 = kk[h][i*3+1], k2 = kk[h][i*3+2];
            cv0 += k0*a   + k1*m.x + k2*m.y;
            cv1 += k0*m.x + k1*m.y + k2*m.z;
            cv2 += k0*m.y + k1*m.z + k2*m.w;
            cv3 += k0*m.z + k1*m.w + k2*e2.x;
        }
        #pragma unroll
        for (int g = 0; g < 8; g++) {
            float wgh = wm[g][h];
            acc[g][0] += wgh * cv0;
            acc[g][1] += wgh * cv1;
            acc[g][2] += wgh * cv2;
            acc[g][3] += wgh * cv3;
        }
    }

    const float m0 = (sq + 0 <= l) ? 1.f : 0.f;
    const float m1 = (sq + 1 <= l) ? 1.f : 0.f;
    const float m2 = (sq + 2 <= l) ? 1.f : 0.f;
    const float m3 = (sq + 3 <= l) ? 1.f : 0.f;

    __half* outb = g_h2 + (size_t)b * 8 * PLANE + (size_t)l * 1024 + sq;
    float es[8];
    #pragma unroll
    for (int g = 0; g < 8; g++) {
        float e0 = __expf(acc[g][0]);
        float e1 = __expf(acc[g][1]);
        float e2v = __expf(acc[g][2]);
        float e3 = __expf(acc[g][3]);
        sth4(&outb[(size_t)g * PLANE], make_float4(e0, e1, e2v, e3));
        es[g] = m0 * e0 + m1 * e1 + m2 * e2v + m3 * e3;
        #pragma unroll
        for (int o = 1; o < 8; o <<= 1)
            es[g] += __shfl_xor_sync(0xffffffffu, es[g], o);
    }
    const int u = tid & 7;
    float val = es[0];
    val = (u == 1) ? es[1] : val;
    val = (u == 2) ? es[2] : val;
    val = (u == 3) ? es[3] : val;
    val = (u == 4) ? es[4] : val;
    val = (u == 5) ? es[5] : val;
    val = (u == 6) ? es[6] : val;
    val = (u == 7) ? es[7] : val;
    g_part[(((size_t)(b * 8 + u) << 10) + l) * 32 + blockIdx.x] = val;
}

// ---------------------------------------------------------------------------
__global__ void __launch_bounds__(256) invz_kernel()
{
    const int row = blockIdx.x * 256 + threadIdx.x;
    const float* p = g_part + (size_t)row * 32;
    float s = 0.f;
    #pragma unroll
    for (int i = 0; i < 8; i++) {
        float4 v = *(const float4*)&p[i << 2];
        s += v.x + v.y + v.z + v.w;
    }
    g_invz[row] = 1.0f / s;
}

// ---------------------------------------------------------------------------
// Pass D (restructured): 32-row x 64-col tiles; each thread computes one
// 8-pixel row segment for both heads of the pair (4 LDS per row-window vs 9
// for two quads). Stages A = E*invZ (causal); conv3x3_after + 2x2 head mix +
// causal zero. Writes A2 fp16. grid (16,32,16): x=s-tile64, y=l-tile32,
// z=b*4+gp. block 256.
// ---------------------------------------------------------------------------
__global__ void __launch_bounds__(256) convhead_kernel(const float* __restrict__ mta_after,
                                                       const float* __restrict__ head_k)
{
    const int st = blockIdx.x << 6, lt = blockIdx.y << 5;
    if (st > lt + 31) return;
    const int b  = blockIdx.z >> 2, gp = blockIdx.z & 3;
    const int tid = threadIdx.x;

    __shared__ __align__(16) float sm[2][34][72];
    __shared__ float kk[2][9];
    __shared__ float hk[4];
    if (tid < 18) kk[tid / 9][tid % 9] = mta_after[18 * gp + tid];
    if (tid >= 32 && tid < 36) hk[tid - 32] = head_k[gp * 4 + (tid - 32)];

    const __half* inb = g_h2 + (size_t)(b * 8 + 2 * gp) * PLANE;
    // halo: rows lt-2..lt+31 (34), cols st-4..st+67 (72) as 18 quads/row
    for (int idx = tid; idx < 2 * 34 * 18; idx += 256) {
        int h   = idx / 612;
        int rem = idx - h * 612;
        int r   = rem / 18;
        int c4  = rem - r * 18;
        int gl  = lt - 2 + r;
        int gs  = st - 4 + (c4 << 2);
        float4 v = make_float4(0.f, 0.f, 0.f, 0.f);
        if (gl >= 0 && gs >= 0 && gs <= 1020) {
            float4 e = ldh4(&inb[(size_t)h * PLANE + (size_t)gl * 1024 + gs]);
            float iz = g_invz[(((size_t)(b * 8 + 2 * gp + h)) << 10) + gl];
            v.x = (gs + 0 <= gl) ? e.x * iz : 0.f;
            v.y = (gs + 1 <= gl) ? e.y * iz : 0.f;
            v.z = (gs + 2 <= gl) ? e.z * iz : 0.f;
            v.w = (gs + 3 <= gl) ? e.w * iz : 0.f;
        }
        *(float4*)&sm[h][r][c4 << 2] = v;
    }
    __syncthreads();

    const int li = tid >> 3;            // 0..31
    const int c0 = (tid & 7) << 3;      // oct base: 0..56
    const int l  = lt + li;
    const int sq = st + c0;

    float cv0[8], cv1[8];
    #pragma unroll
    for (int p = 0; p < 8; p++) { cv0[p] = 0.f; cv1[p] = 0.f; }

    #pragma unroll
    for (int hh = 0; hh < 2; hh++) {
        float* cv = hh ? cv1 : cv0;
        #pragma unroll
        for (int i = 0; i < 3; i++) {
            const float* rp = &sm[hh][li + i][c0];
            // window cols sq-1 .. sq+8 = local c0+3 .. c0+12
            float  w0 = rp[3];
            float4 wa = *(const float4*)(rp + 4);
            float4 wb = *(const float4*)(rp + 8);
            float  wc = rp[12];
            float k0 = kk[hh][i*3+0], k1 = kk[hh][i*3+1], k2 = kk[hh][i*3+2];
            cv[0] += k0*w0   + k1*wa.x + k2*wa.y;
            cv[1] += k0*wa.x + k1*wa.y + k2*wa.z;
            cv[2] += k0*wa.y + k1*wa.z + k2*wa.w;
            cv[3] += k0*wa.z + k1*wa.w + k2*wb.x;
            cv[4] += k0*wa.w + k1*wb.x + k2*wb.y;
            cv[5] += k0*wb.x + k1*wb.y + k2*wb.z;
            cv[6] += k0*wb.y + k1*wb.z + k2*wb.w;
            cv[7] += k0*wb.z + k1*wb.w + k2*wc;
        }
    }

    float h00 = hk[0], h01 = hk[1], h10 = hk[2], h11 = hk[3];
    float o0[8], o1[8];
    #pragma unroll
    for (int p = 0; p < 8; p++) {
        float cz = (sq + p <= l) ? 1.f : 0.f;
        o0[p] = (cv0[p] * h00 + cv1[p] * h10) * cz;
        o1[p] = (cv0[p] * h01 + cv1[p] * h11) * cz;
    }

    __half* outb = g_h1 + (size_t)(b * 8 + 2 * gp) * PLANE + (size_t)l * 1024 + sq;
    sth4(&outb[0],         make_float4(o0[0], o0[1], o0[2], o0[3]));
    sth4(&outb[4],         make_float4(o0[4], o0[5], o0[6], o0[7]));
    sth4(&outb[PLANE],     make_float4(o1[0], o1[1], o1[2], o1[3]));
    sth4(&outb[PLANE + 4], make_float4(o1[4], o1[5], o1[6], o1[7]));
}

// ---------------------------------------------------------------------------
// Pass E: out = A2 @ V via fp16 HMMA, PAIRED for load balance (sub-blocks of
// 128 threads via named barriers; tiles t and 31-t per block -> uniform cost).
// A2 above-diagonal is zero, so the overshooting diagonal s-tile is safe.
// grid (32, 16): x = bh, y = pair p. block 256.
// ---------------------------------------------------------------------------
#define AV_AST 72
__global__ void __launch_bounds__(256) av_kernel(const float* __restrict__ v,
                                                 float* __restrict__ out)
{
    const int bh = blockIdx.x;
    const int b  = bh >> 3, h = bh & 7;
    const int p  = blockIdx.y;
    const int tid = threadIdx.x;
    const int half = tid >> 7;
    const int st   = tid & 127;
    const int t    = half ? (31 - p) : p;
    const int l0   = t << 5;
    const int wrp = st >> 5, lane = st & 31;
    const int gid = lane >> 2, tg = lane & 3;
    const int m0  = (wrp & 1) << 4;
    const int n0  = (wrp >> 1) << 5;
    const int bar = 1 + half;

    __shared__ __align__(16) __half  As[2][32][AV_AST];
    __shared__ __align__(16) __half2 Vp[2][64][33];
    const __half* Ab = g_h1 + (size_t)bh * PLANE;
    const float*  vb = v + (size_t)b * L_ * 512 + h * 64;

    float acc[4][4];
    #pragma unroll
    for (int j = 0; j < 4; j++)
        #pragma unroll
        for (int i = 0; i < 4; i++) acc[j][i] = 0.f;

    const int n_iter = (l0 >> 6) + 1;
    for (int it = 0; it < n_iter; it++) {
        const int s0 = it << 6;
        #pragma unroll
        for (int i = 0; i < 4; i++) {
            int idx = st + (i << 7);
            int row = idx >> 4;
            int c   = (idx & 15) << 2;
            *(uint2*)&As[half][row][c] =
                *(const uint2*)&Ab[(size_t)(l0 + row) * 1024 + s0 + c];
        }
        #pragma unroll
        for (int i = 0; i < 4; i++) {
            int idx = st + (i << 7);
            int s2  = idx >> 4;
            int e   = (idx & 15) << 2;
            float4 va = *(const float4*)&vb[(size_t)(s0 + 2 * s2) * 512 + e];
            float4 vc = *(const float4*)&vb[(size_t)(s0 + 2 * s2 + 1) * 512 + e];
            Vp[half][e + 0][s2] = __floats2half2_rn(va.x, vc.x);
            Vp[half][e + 1][s2] = __floats2half2_rn(va.y, vc.y);
            Vp[half][e + 2][s2] = __floats2half2_rn(va.z, vc.z);
            Vp[half][e + 3][s2] = __floats2half2_rn(va.w, vc.w);
        }
        BAR_SYNC_HALF(bar);

        #pragma unroll
        for (int k0 = 0; k0 < 64; k0 += 16) {
            uint32_t a0 = *(const uint32_t*)&As[half][m0 + gid][k0 + 2 * tg];
            uint32_t a1 = *(const uint32_t*)&As[half][m0 + gid + 8][k0 + 2 * tg];
            uint32_t a2 = *(const uint32_t*)&As[half][m0 + gid][k0 + 2 * tg + 8];
            uint32_t a3 = *(const uint32_t*)&As[half][m0 + gid + 8][k0 + 2 * tg + 8];
            int sp = k0 >> 1;
            #pragma unroll
            for (int j = 0; j < 4; j++) {
                int nb = n0 + (j << 3);
                uint32_t b0 = *(const uint32_t*)&Vp[half][nb + gid][sp + tg];
                uint32_t b1 = *(const uint32_t*)&Vp[half][nb + gid][sp + tg + 4];
                mma_f16(acc[j], a0, a1, a2, a3, b0, b1);
            }
        }
        BAR_SYNC_HALF(bar);
    }

    #pragma unroll
    for (int j = 0; j < 4; j++) {
        int e  = n0 + (j << 3) + (tg << 1);
        int l1 = l0 + m0 + gid;
        int l2 = l1 + 8;
        *(float2*)&out[((size_t)(b * L_ + l1) * H_ + h) * 64 + e] =
            make_float2(acc[j][0], acc[j][1]);
        *(float2*)&out[((size_t)(b * L_ + l2) * H_ + h) * 64 + e] =
            make_float2(acc[j][2], acc[j][3]);
    }
}

// ---------------------------------------------------------------------------
extern "C" void kernel_launch(void* const* d_in, const int* in_sizes, int n_in,
                              void* d_out, int out_size)
{
    const float* q         = (const float*)d_in[0];
    const float* k         = (const float*)d_in[1];
    const float* v         = (const float*)d_in[2];
    const float* mta       = (const float*)d_in[3];
    const float* mta_after = (const float*)d_in[4];
    const float* head_k    = (const float*)d_in[5];
    const float* wpsm      = (const float*)d_in[6];
    float* out = (float*)d_out;

    dim3 gA(16, 16, 32);
    qk_kernel<<<gA, 256>>>(q, k);

    dim3 gB(32, 32, 4);
    convmix_kernel<<<gB, 256>>>(mta, wpsm);

    invz_kernel<<<128, 256>>>();

    dim3 gD(16, 32, 16);
    convhead_kernel<<<gD, 256>>>(mta_after, head_k);

    dim3 gE(32, 16);
    av_kernel<<<gE, 256>>>(v, out);
}

// round 14
// speedup vs baseline: 1.0119x; 1.0119x over previous
#include <cuda_runtime.h>
#include <cuda_fp16.h>
#include <cstdint>

#define B_ 4
#define L_ 1024
#define H_ 8
#define PLANE (1024*1024)

// fp16 scratch planes (64 MB each, zero-initialized .bss). Never-written
// regions (strictly-above-diagonal tiles) stay 0x0000 = +0.0h deterministically.
__device__ __half g_h1[(size_t)B_*H_*L_*L_];   // S1, then A2
__device__ __half g_h2[(size_t)B_*H_*L_*L_];   // E = exp(S2)
__device__ float  g_part[(size_t)B_*H_*L_*32];
__device__ float  g_invz[(size_t)B_*H_*L_];

__device__ __forceinline__ void mma_f16(float c[4],
                                        uint32_t a0, uint32_t a1, uint32_t a2, uint32_t a3,
                                        uint32_t b0, uint32_t b1) {
    asm volatile(
        "mma.sync.aligned.m16n8k16.row.col.f32.f16.f16.f32 "
        "{%0,%1,%2,%3}, {%4,%5,%6,%7}, {%8,%9}, {%0,%1,%2,%3};"
        : "+f"(c[0]), "+f"(c[1]), "+f"(c[2]), "+f"(c[3])
        : "r"(a0), "r"(a1), "r"(a2), "r"(a3), "r"(b0), "r"(b1));
}

__device__ __forceinline__ float4 ldh4(const __half* p) {
    uint2 u = *(const uint2*)p;
    __half2 h0 = *(__half2*)&u.x;
    __half2 h1 = *(__half2*)&u.y;
    float2 f0 = __half22float2(h0);
    float2 f1 = __half22float2(h1);
    return make_float4(f0.x, f0.y, f1.x, f1.y);
}

__device__ __forceinline__ void sth4(__half* p, float4 v) {
    __half2 a = __floats2half2_rn(v.x, v.y);
    __half2 b = __floats2half2_rn(v.z, v.w);
    uint2 u;
    u.x = *(uint32_t*)&a;
    u.y = *(uint32_t*)&b;
    *(uint2*)p = u;
}

#define BAR_SYNC_HALF(id) asm volatile("bar.sync %0, %1;" :: "r"(id), "r"(128) : "memory")

// ---------------------------------------------------------------------------
// Pass A: S1 = (Q.K^T)*scale via fp16 HMMA (fp32 accum); causal zeroed;
// masked tiles skipped. Output fp16. grid (16,16,32), block 256.
// ---------------------------------------------------------------------------
#define QK_ST 72
__global__ void __launch_bounds__(256) qk_kernel(const float* __restrict__ q,
                                                 const float* __restrict__ k)
{
    const int bh = blockIdx.z;
    const int b  = bh >> 3, h = bh & 7;
    const int l0 = blockIdx.y << 6, s0 = blockIdx.x << 6;
    if (s0 > l0 + 63) return;

    const int tid  = threadIdx.x;
    const int wrp  = tid >> 5, lane = tid & 31;
    const int gid  = lane >> 2, tg = lane & 3;
    const int m0   = (wrp & 3) << 4;
    const int n0   = (wrp >> 2) << 5;

    __shared__ __align__(16) __half Qs[64][QK_ST];
    __shared__ __align__(16) __half Ks[64][QK_ST];
    __shared__ __align__(16) float Cs[64][68];
    const float* qb = q + (size_t)b * L_ * 512 + h * 64;
    const float* kb = k + (size_t)b * L_ * 512 + h * 64;

    #pragma unroll
    for (int i = 0; i < 4; i++) {
        int row = (tid >> 4) + (i << 4);
        int c   = (tid & 15) << 2;
        sth4(&Qs[row][c], *(const float4*)&qb[(size_t)(l0 + row) * 512 + c]);
        sth4(&Ks[row][c], *(const float4*)&kb[(size_t)(s0 + row) * 512 + c]);
    }
    __syncthreads();

    float acc[4][4];
    #pragma unroll
    for (int j = 0; j < 4; j++)
        #pragma unroll
        for (int i = 0; i < 4; i++) acc[j][i] = 0.f;

    #pragma unroll
    for (int e0 = 0; e0 < 64; e0 += 16) {
        uint32_t a0 = *(const uint32_t*)&Qs[m0 + gid][e0 + 2 * tg];
        uint32_t a1 = *(const uint32_t*)&Qs[m0 + gid + 8][e0 + 2 * tg];
        uint32_t a2 = *(const uint32_t*)&Qs[m0 + gid][e0 + 2 * tg + 8];
        uint32_t a3 = *(const uint32_t*)&Qs[m0 + gid + 8][e0 + 2 * tg + 8];
        #pragma unroll
        for (int j = 0; j < 4; j++) {
            int nb = n0 + (j << 3);
            uint32_t b0 = *(const uint32_t*)&Ks[nb + gid][e0 + 2 * tg];
            uint32_t b1 = *(const uint32_t*)&Ks[nb + gid][e0 + 2 * tg + 8];
            mma_f16(acc[j], a0, a1, a2, a3, b0, b1);
        }
    }
    __syncthreads();

    #pragma unroll
    for (int j = 0; j < 4; j++) {
        int nb = n0 + (j << 3) + (tg << 1);
        Cs[m0 + gid][nb]         = acc[j][0];
        Cs[m0 + gid][nb + 1]     = acc[j][1];
        Cs[m0 + gid + 8][nb]     = acc[j][2];
        Cs[m0 + gid + 8][nb + 1] = acc[j][3];
    }
    __syncthreads();

    __half* outp = g_h1 + (size_t)bh * PLANE;
    const float scale = 0.125f;
    #pragma unroll
    for (int i = 0; i < 4; i++) {
        int row = (tid >> 4) + (i << 4);
        int c   = (tid & 15) << 2;
        int l   = l0 + row, sb = s0 + c;
        float4 v = *(const float4*)&Cs[row][c];
        float4 r;
        r.x = (sb + 0 <= l) ? v.x * scale : 0.f;
        r.y = (sb + 1 <= l) ? v.y * scale : 0.f;
        r.z = (sb + 2 <= l) ? v.z * scale : 0.f;
        r.w = (sb + 3 <= l) ? v.w * scale : 0.f;
        sth4(&outp[(size_t)l * 1024 + sb], r);
    }
}

// ---------------------------------------------------------------------------
// Pass B: S2[b,g] = sum_h wpsm[g,h]*conv3x3(S1[b,h]); writes E = exp(S2) (fp16)
// and per-row causal-masked partial sums of exp. TWO-PHASE head staging:
// heads 0-3 then 4-7 through a half-size smem buffer (21.8 KB -> 2x occupancy).
// grid (32,32,4), block 256, quad per thread.
// ---------------------------------------------------------------------------
__global__ void __launch_bounds__(256) convmix_kernel(const float* __restrict__ mta_k,
                                                      const float* __restrict__ wpsm)
{
    if (blockIdx.x > blockIdx.y) return;
    const int st = blockIdx.x << 5, lt = blockIdx.y << 5, b = blockIdx.z;
    const int tid = threadIdx.x;

    __shared__ __align__(16) float sm[4][34][40];
    __shared__ float kk[8][9];
    __shared__ float wm[8][8];
    if (tid < 72) kk[tid / 9][tid % 9] = mta_k[tid];
    if (tid >= 128 && tid < 192) { int t = tid - 128; wm[t >> 3][t & 7] = wpsm[t]; }

    const __half* inb = g_h1 + (size_t)b * 8 * PLANE;
    const int li = tid >> 3;
    const int c0 = (tid & 7) << 2;
    const int l  = lt + li;
    const int sq = st + c0;

    float acc[8][4];
    #pragma unroll
    for (int g = 0; g < 8; g++)
        #pragma unroll
        for (int j = 0; j < 4; j++) acc[g][j] = 0.f;

    #pragma unroll 1
    for (int phase = 0; phase < 2; phase++) {
        // stage heads 4*phase .. 4*phase+3
        for (int idx = tid; idx < 4 * 34 * 10; idx += 256) {
            int hh  = idx / 340;
            int rem = idx - hh * 340;
            int r   = rem / 10;
            int c4  = rem - r * 10;
            int gl  = lt - 2 + r;
            int gs  = st - 4 + (c4 << 2);
            float4 v = make_float4(0.f, 0.f, 0.f, 0.f);
            if (gl >= 0 && gs >= 0 && gs <= 1020)
                v = ldh4(&inb[(size_t)(4 * phase + hh) * PLANE + (size_t)gl * 1024 + gs]);
            *(float4*)&sm[hh][r][c4 << 2] = v;
        }
        __syncthreads();

        #pragma unroll 1
        for (int hh = 0; hh < 4; hh++) {
            const int h = 4 * phase + hh;
            float cv0 = 0.f, cv1 = 0.f, cv2 = 0.f, cv3 = 0.f;
            #pragma unroll
            for (int i = 0; i < 3; i++) {
                const float* rp = &sm[hh][li + i][c0];
                float  a  = rp[3];
                float4 m  = *(const float4*)(rp + 4);
                float2 e2 = *(const float2*)(rp + 8);
                float k0 = kk[h][i*3+0], k1 = kk[h][i*3+1], k2 = kk[h][i*3+2];
                cv0 += k0*a   + k1*m.x + k2*m.y;
                cv1 += k0*m.x + k1*m.y + k2*m.z;
                cv2 += k0*m.y + k1*m.z + k2*m.w;
                cv3 += k0*m.z + k1*m.w + k2*e2.x;
            }
            #pragma unroll
            for (int g = 0; g < 8; g++) {
                float wgh = wm[g][h];
                acc[g][0] += wgh * cv0;
                acc[g][1] += wgh * cv1;
                acc[g][2] += wgh * cv2;
                acc[g][3] += wgh * cv3;
            }
        }
        __syncthreads();   // protect sm before next phase's staging
    }

    const float m0 = (sq + 0 <= l) ? 1.f : 0.f;
    const float m1 = (sq + 1 <= l) ? 1.f : 0.f;
    const float m2 = (sq + 2 <= l) ? 1.f : 0.f;
    const float m3 = (sq + 3 <= l) ? 1.f : 0.f;

    __half* outb = g_h2 + (size_t)b * 8 * PLANE + (size_t)l * 1024 + sq;
    float es[8];
    #pragma unroll
    for (int g = 0; g < 8; g++) {
        float e0 = __expf(acc[g][0]);
        float e1 = __expf(acc[g][1]);
        float e2v = __expf(acc[g][2]);
        float e3 = __expf(acc[g][3]);
        sth4(&outb[(size_t)g * PLANE], make_float4(e0, e1, e2v, e3));
        es[g] = m0 * e0 + m1 * e1 + m2 * e2v + m3 * e3;
        #pragma unroll
        for (int o = 1; o < 8; o <<= 1)
            es[g] += __shfl_xor_sync(0xffffffffu, es[g], o);
    }
    const int u = tid & 7;
    float val = es[0];
    val = (u == 1) ? es[1] : val;
    val = (u == 2) ? es[2] : val;
    val = (u == 3) ? es[3] : val;
    val = (u == 4) ? es[4] : val;
    val = (u == 5) ? es[5] : val;
    val = (u == 6) ? es[6] : val;
    val = (u == 7) ? es[7] : val;
    g_part[(((size_t)(b * 8 + u) << 10) + l) * 32 + blockIdx.x] = val;
}

// ---------------------------------------------------------------------------
__global__ void __launch_bounds__(256) invz_kernel()
{
    const int row = blockIdx.x * 256 + threadIdx.x;
    const float* p = g_part + (size_t)row * 32;
    float s = 0.f;
    #pragma unroll
    for (int i = 0; i < 8; i++) {
        float4 v = *(const float4*)&p[i << 2];
        s += v.x + v.y + v.z + v.w;
    }
    g_invz[row] = 1.0f / s;
}

// ---------------------------------------------------------------------------
// Pass D (R11-proven): split per head-pair; stages A = E*invZ (causal);
// conv3x3_after + 2x2 head mix + causal zero. Writes A2 fp16.
// grid (32,32,16): z = b*4+gp. block 256.
// ---------------------------------------------------------------------------
__global__ void __launch_bounds__(256) convhead_kernel(const float* __restrict__ mta_after,
                                                       const float* __restrict__ head_k)
{
    if (blockIdx.x > blockIdx.y) return;
    const int st = blockIdx.x << 5, lt = blockIdx.y << 5;
    const int b  = blockIdx.z >> 2, gp = blockIdx.z & 3;
    const int tid = threadIdx.x;

    __shared__ __align__(16) float sm[2][34][40];
    __shared__ float kk[2][9];
    __shared__ float hk[4];
    if (tid < 18) kk[tid / 9][tid % 9] = mta_after[18 * gp + tid];
    if (tid >= 32 && tid < 36) hk[tid - 32] = head_k[gp * 4 + (tid - 32)];

    const __half* inb = g_h2 + (size_t)(b * 8 + 2 * gp) * PLANE;
    for (int idx = tid; idx < 2 * 34 * 10; idx += 256) {
        int h   = idx / 340;
        int rem = idx - h * 340;
        int r   = rem / 10;
        int c4  = rem - r * 10;
        int gl  = lt - 2 + r;
        int gs  = st - 4 + (c4 << 2);
        float4 v = make_float4(0.f, 0.f, 0.f, 0.f);
        if (gl >= 0 && gs >= 0 && gs <= 1020) {
            float4 e = ldh4(&inb[(size_t)h * PLANE + (size_t)gl * 1024 + gs]);
            float iz = g_invz[(((size_t)(b * 8 + 2 * gp + h)) << 10) + gl];
            v.x = (gs + 0 <= gl) ? e.x * iz : 0.f;
            v.y = (gs + 1 <= gl) ? e.y * iz : 0.f;
            v.z = (gs + 2 <= gl) ? e.z * iz : 0.f;
            v.w = (gs + 3 <= gl) ? e.w * iz : 0.f;
        }
        *(float4*)&sm[h][r][c4 << 2] = v;
    }
    __syncthreads();

    const int li = tid >> 3;
    const int c0 = (tid & 7) << 2;
    const int l  = lt + li;
    const int sq = st + c0;
    const float cz0 = (sq + 0 <= l) ? 1.f : 0.f;
    const float cz1 = (sq + 1 <= l) ? 1.f : 0.f;
    const float cz2 = (sq + 2 <= l) ? 1.f : 0.f;
    const float cz3 = (sq + 3 <= l) ? 1.f : 0.f;

    float c0v[4] = {0.f, 0.f, 0.f, 0.f};
    float c1v[4] = {0.f, 0.f, 0.f, 0.f};
    #pragma unroll
    for (int hh = 0; hh < 2; hh++) {
        float* cv = hh ? c1v : c0v;
        #pragma unroll
        for (int i = 0; i < 3; i++) {
            const float* rp = &sm[hh][li + i][c0];
            float  a  = rp[3];
            float4 m  = *(const float4*)(rp + 4);
            float2 e2 = *(const float2*)(rp + 8);
            float k0 = kk[hh][i*3+0], k1 = kk[hh][i*3+1], k2 = kk[hh][i*3+2];
            cv[0] += k0*a   + k1*m.x + k2*m.y;
            cv[1] += k0*m.x + k1*m.y + k2*m.z;
            cv[2] += k0*m.y + k1*m.z + k2*m.w;
            cv[3] += k0*m.z + k1*m.w + k2*e2.x;
        }
    }
    float h00 = hk[0], h01 = hk[1], h10 = hk[2], h11 = hk[3];
    __half* outb = g_h1 + (size_t)(b * 8 + 2 * gp) * PLANE + (size_t)l * 1024 + sq;
    sth4(&outb[0],
         make_float4((c0v[0]*h00 + c1v[0]*h10) * cz0,
                     (c0v[1]*h00 + c1v[1]*h10) * cz1,
                     (c0v[2]*h00 + c1v[2]*h10) * cz2,
                     (c0v[3]*h00 + c1v[3]*h10) * cz3));
    sth4(&outb[PLANE],
         make_float4((c0v[0]*h01 + c1v[0]*h11) * cz0,
                     (c0v[1]*h01 + c1v[1]*h11) * cz1,
                     (c0v[2]*h01 + c1v[2]*h11) * cz2,
                     (c0v[3]*h01 + c1v[3]*h11) * cz3));
}

// ---------------------------------------------------------------------------
// Pass E: out = A2 @ V via fp16 HMMA, PAIRED for load balance (two 128-thread
// sub-blocks on named barriers; tiles t and 31-t per block -> uniform cost).
// A2 above-diagonal is zero, so the overshooting diagonal s-tile is safe.
// grid (32, 16): x = bh, y = pair p. block 256.
// ---------------------------------------------------------------------------
#define AV_AST 72
__global__ void __launch_bounds__(256) av_kernel(const float* __restrict__ v,
                                                 float* __restrict__ out)
{
    const int bh = blockIdx.x;
    const int b  = bh >> 3, h = bh & 7;
    const int p  = blockIdx.y;
    const int tid = threadIdx.x;
    const int half = tid >> 7;
    const int st   = tid & 127;
    const int t    = half ? (31 - p) : p;
    const int l0   = t << 5;
    const int wrp = st >> 5, lane = st & 31;
    const int gid = lane >> 2, tg = lane & 3;
    const int m0  = (wrp & 1) << 4;
    const int n0  = (wrp >> 1) << 5;
    const int bar = 1 + half;

    __shared__ __align__(16) __half  As[2][32][AV_AST];
    __shared__ __align__(16) __half2 Vp[2][64][33];
    const __half* Ab = g_h1 + (size_t)bh * PLANE;
    const float*  vb = v + (size_t)b * L_ * 512 + h * 64;

    float acc[4][4];
    #pragma unroll
    for (int j = 0; j < 4; j++)
        #pragma unroll
        for (int i = 0; i < 4; i++) acc[j][i] = 0.f;

    const int n_iter = (l0 >> 6) + 1;
    for (int it = 0; it < n_iter; it++) {
        const int s0 = it << 6;
        #pragma unroll
        for (int i = 0; i < 4; i++) {
            int idx = st + (i << 7);
            int row = idx >> 4;
            int c   = (idx & 15) << 2;
            *(uint2*)&As[half][row][c] =
                *(const uint2*)&Ab[(size_t)(l0 + row) * 1024 + s0 + c];
        }
        #pragma unroll
        for (int i = 0; i < 4; i++) {
            int idx = st + (i << 7);
            int s2  = idx >> 4;
            int e   = (idx & 15) << 2;
            float4 va = *(const float4*)&vb[(size_t)(s0 + 2 * s2) * 512 + e];
            float4 vc = *(const float4*)&vb[(size_t)(s0 + 2 * s2 + 1) * 512 + e];
            Vp[half][e + 0][s2] = __floats2half2_rn(va.x, vc.x);
            Vp[half][e + 1][s2] = __floats2half2_rn(va.y, vc.y);
            Vp[half][e + 2][s2] = __floats2half2_rn(va.z, vc.z);
            Vp[half][e + 3][s2] = __floats2half2_rn(va.w, vc.w);
        }
        BAR_SYNC_HALF(bar);

        #pragma unroll
        for (int k0 = 0; k0 < 64; k0 += 16) {
            uint32_t a0 = *(const uint32_t*)&As[half][m0 + gid][k0 + 2 * tg];
            uint32_t a1 = *(const uint32_t*)&As[half][m0 + gid + 8][k0 + 2 * tg];
            uint32_t a2 = *(const uint32_t*)&As[half][m0 + gid][k0 + 2 * tg + 8];
            uint32_t a3 = *(const uint32_t*)&As[half][m0 + gid + 8][k0 + 2 * tg + 8];
            int sp = k0 >> 1;
            #pragma unroll
            for (int j = 0; j < 4; j++) {
                int nb = n0 + (j << 3);
                uint32_t b0 = *(const uint32_t*)&Vp[half][nb + gid][sp + tg];
                uint32_t b1 = *(const uint32_t*)&Vp[half][nb + gid][sp + tg + 4];
                mma_f16(acc[j], a0, a1, a2, a3, b0, b1);
            }
        }
        BAR_SYNC_HALF(bar);
    }

    #pragma unroll
    for (int j = 0; j < 4; j++) {
        int e  = n0 + (j << 3) + (tg << 1);
        int l1 = l0 + m0 + gid;
        int l2 = l1 + 8;
        *(float2*)&out[((size_t)(b * L_ + l1) * H_ + h) * 64 + e] =
            make_float2(acc[j][0], acc[j][1]);
        *(float2*)&out[((size_t)(b * L_ + l2) * H_ + h) * 64 + e] =
            make_float2(acc[j][2], acc[j][3]);
    }
}

// ---------------------------------------------------------------------------
extern "C" void kernel_launch(void* const* d_in, const int* in_sizes, int n_in,
                              void* d_out, int out_size)
{
    const float* q         = (const float*)d_in[0];
    const float* k         = (const float*)d_in[1];
    const float* v         = (const float*)d_in[2];
    const float* mta       = (const float*)d_in[3];
    const float* mta_after = (const float*)d_in[4];
    const float* head_k    = (const float*)d_in[5];
    const float* wpsm      = (const float*)d_in[6];
    float* out = (float*)d_out;

    dim3 gA(16, 16, 32);
    qk_kernel<<<gA, 256>>>(q, k);

    dim3 gB(32, 32, 4);
    convmix_kernel<<<gB, 256>>>(mta, wpsm);

    invz_kernel<<<128, 256>>>();

    dim3 gD(32, 32, 16);
    convhead_kernel<<<gD, 256>>>(mta_after, head_k);

    dim3 gE(32, 16);
    av_kernel<<<gE, 256>>>(v, out);
}

// round 15
// speedup vs baseline: 1.0248x; 1.0128x over previous
#include <cuda_runtime.h>
#include <cuda_fp16.h>
#include <cstdint>

#define B_ 4
#define L_ 1024
#define H_ 8
#define PLANE (1024*1024)

// fp16 scratch planes (64 MB each, zero-initialized .bss). Never-written
// regions (strictly-above-diagonal tiles) stay 0x0000 = +0.0h deterministically.
__device__ __half g_h1[(size_t)B_*H_*L_*L_];   // S1, then A2
__device__ __half g_h2[(size_t)B_*H_*L_*L_];   // Ehat = exp(S2), causally masked
__device__ float  g_part[(size_t)B_*H_*L_*32];
__device__ float  g_invz[(size_t)B_*H_*L_];

__device__ __forceinline__ void mma_f16(float c[4],
                                        uint32_t a0, uint32_t a1, uint32_t a2, uint32_t a3,
                                        uint32_t b0, uint32_t b1) {
    asm volatile(
        "mma.sync.aligned.m16n8k16.row.col.f32.f16.f16.f32 "
        "{%0,%1,%2,%3}, {%4,%5,%6,%7}, {%8,%9}, {%0,%1,%2,%3};"
        : "+f"(c[0]), "+f"(c[1]), "+f"(c[2]), "+f"(c[3])
        : "r"(a0), "r"(a1), "r"(a2), "r"(a3), "r"(b0), "r"(b1));
}

__device__ __forceinline__ float4 ldh4(const __half* p) {
    uint2 u = *(const uint2*)p;
    __half2 h0 = *(__half2*)&u.x;
    __half2 h1 = *(__half2*)&u.y;
    float2 f0 = __half22float2(h0);
    float2 f1 = __half22float2(h1);
    return make_float4(f0.x, f0.y, f1.x, f1.y);
}

__device__ __forceinline__ void sth4(__half* p, float4 v) {
    __half2 a = __floats2half2_rn(v.x, v.y);
    __half2 b = __floats2half2_rn(v.z, v.w);
    uint2 u;
    u.x = *(uint32_t*)&a;
    u.y = *(uint32_t*)&b;
    *(uint2*)p = u;
}

__device__ __forceinline__ unsigned long long pack_f32x2(float lo, float hi) {
    unsigned long long r;
    asm("mov.b64 %0, {%1, %2};" : "=l"(r) : "f"(lo), "f"(hi));
    return r;
}
__device__ __forceinline__ void unpack_f32x2(float& lo, float& hi, unsigned long long v) {
    asm("mov.b64 {%0, %1}, %2;" : "=f"(lo), "=f"(hi) : "l"(v));
}
__device__ __forceinline__ unsigned long long fma_f32x2(unsigned long long a,
                                                        unsigned long long b,
                                                        unsigned long long c) {
    unsigned long long r;
    asm("fma.rn.f32x2 %0, %1, %2, %3;" : "=l"(r) : "l"(a), "l"(b), "l"(c));
    return r;
}

#define BAR_SYNC_HALF(id) asm volatile("bar.sync %0, %1;" :: "r"(id), "r"(128) : "memory")

// ---------------------------------------------------------------------------
// Pass A: S1 = (Q.K^T)*scale via fp16 HMMA (fp32 accum); causal zeroed;
// masked tiles skipped. Output fp16. grid (16,16,32), block 256.
// ---------------------------------------------------------------------------
#define QK_ST 72
__global__ void __launch_bounds__(256) qk_kernel(const float* __restrict__ q,
                                                 const float* __restrict__ k)
{
    const int bh = blockIdx.z;
    const int b  = bh >> 3, h = bh & 7;
    const int l0 = blockIdx.y << 6, s0 = blockIdx.x << 6;
    if (s0 > l0 + 63) return;

    const int tid  = threadIdx.x;
    const int wrp  = tid >> 5, lane = tid & 31;
    const int gid  = lane >> 2, tg = lane & 3;
    const int m0   = (wrp & 3) << 4;
    const int n0   = (wrp >> 2) << 5;

    __shared__ __align__(16) __half Qs[64][QK_ST];
    __shared__ __align__(16) __half Ks[64][QK_ST];
    __shared__ __align__(16) float Cs[64][68];
    const float* qb = q + (size_t)b * L_ * 512 + h * 64;
    const float* kb = k + (size_t)b * L_ * 512 + h * 64;

    #pragma unroll
    for (int i = 0; i < 4; i++) {
        int row = (tid >> 4) + (i << 4);
        int c   = (tid & 15) << 2;
        sth4(&Qs[row][c], *(const float4*)&qb[(size_t)(l0 + row) * 512 + c]);
        sth4(&Ks[row][c], *(const float4*)&kb[(size_t)(s0 + row) * 512 + c]);
    }
    __syncthreads();

    float acc[4][4];
    #pragma unroll
    for (int j = 0; j < 4; j++)
        #pragma unroll
        for (int i = 0; i < 4; i++) acc[j][i] = 0.f;

    #pragma unroll
    for (int e0 = 0; e0 < 64; e0 += 16) {
        uint32_t a0 = *(const uint32_t*)&Qs[m0 + gid][e0 + 2 * tg];
        uint32_t a1 = *(const uint32_t*)&Qs[m0 + gid + 8][e0 + 2 * tg];
        uint32_t a2 = *(const uint32_t*)&Qs[m0 + gid][e0 + 2 * tg + 8];
        uint32_t a3 = *(const uint32_t*)&Qs[m0 + gid + 8][e0 + 2 * tg + 8];
        #pragma unroll
        for (int j = 0; j < 4; j++) {
            int nb = n0 + (j << 3);
            uint32_t b0 = *(const uint32_t*)&Ks[nb + gid][e0 + 2 * tg];
            uint32_t b1 = *(const uint32_t*)&Ks[nb + gid][e0 + 2 * tg + 8];
            mma_f16(acc[j], a0, a1, a2, a3, b0, b1);
        }
    }
    __syncthreads();

    #pragma unroll
    for (int j = 0; j < 4; j++) {
        int nb = n0 + (j << 3) + (tg << 1);
        Cs[m0 + gid][nb]         = acc[j][0];
        Cs[m0 + gid][nb + 1]     = acc[j][1];
        Cs[m0 + gid + 8][nb]     = acc[j][2];
        Cs[m0 + gid + 8][nb + 1] = acc[j][3];
    }
    __syncthreads();

    __half* outp = g_h1 + (size_t)bh * PLANE;
    const float scale = 0.125f;
    #pragma unroll
    for (int i = 0; i < 4; i++) {
        int row = (tid >> 4) + (i << 4);
        int c   = (tid & 15) << 2;
        int l   = l0 + row, sb = s0 + c;
        float4 v = *(const float4*)&Cs[row][c];
        float4 r;
        r.x = (sb + 0 <= l) ? v.x * scale : 0.f;
        r.y = (sb + 1 <= l) ? v.y * scale : 0.f;
        r.z = (sb + 2 <= l) ? v.z * scale : 0.f;
        r.w = (sb + 3 <= l) ? v.w * scale : 0.f;
        sth4(&outp[(size_t)l * 1024 + sb], r);
    }
}

// ---------------------------------------------------------------------------
// Pass B: S2[b,g] = sum_h wpsm[g,h]*conv3x3(S1[b,h]); writes Ehat = MASKED
// exp(S2) (fp16) and per-row partial sums of exp to g_part.
// Mix uses packed f32x2 FMA (IEEE-identical to scalar fp32 FMA).
// grid (32,32,4), block 256, quad per thread.
// ---------------------------------------------------------------------------
__global__ void __launch_bounds__(256) convmix_kernel(const float* __restrict__ mta_k,
                                                      const float* __restrict__ wpsm)
{
    if (blockIdx.x > blockIdx.y) return;
    const int st = blockIdx.x << 5, lt = blockIdx.y << 5, b = blockIdx.z;
    const int tid = threadIdx.x;

    __shared__ __align__(16) float sm[8][34][40];
    __shared__ float kk[8][9];
    __shared__ unsigned long long wm2[8][8];   // dual-lane broadcast of wpsm
    if (tid < 72) kk[tid / 9][tid % 9] = mta_k[tid];
    if (tid >= 128 && tid < 192) {
        int t = tid - 128;
        float w = wpsm[t];
        wm2[t >> 3][t & 7] = pack_f32x2(w, w);
    }

    const __half* inb = g_h1 + (size_t)b * 8 * PLANE;
    for (int idx = tid; idx < 8 * 34 * 10; idx += 256) {
        int h   = idx / 340;
        int rem = idx - h * 340;
        int r   = rem / 10;
        int c4  = rem - r * 10;
        int gl  = lt - 2 + r;
        int gs  = st - 4 + (c4 << 2);
        float4 v = make_float4(0.f, 0.f, 0.f, 0.f);
        if (gl >= 0 && gs >= 0 && gs <= 1020)
            v = ldh4(&inb[(size_t)h * PLANE + (size_t)gl * 1024 + gs]);
        *(float4*)&sm[h][r][c4 << 2] = v;
    }
    __syncthreads();

    const int li = tid >> 3;
    const int c0 = (tid & 7) << 2;
    const int l  = lt + li;
    const int sq = st + c0;

    unsigned long long accl[8], acch[8];   // f32x2 pairs: (px0,px1), (px2,px3)
    #pragma unroll
    for (int g = 0; g < 8; g++) { accl[g] = 0ull; acch[g] = 0ull; }

    #pragma unroll 1
    for (int h = 0; h < 8; h++) {
        float cv0 = 0.f, cv1 = 0.f, cv2 = 0.f, cv3 = 0.f;
        #pragma unroll
        for (int i = 0; i < 3; i++) {
            const float* rp = &sm[h][li + i][c0];
            float  a  = rp[3];
            float4 m  = *(const float4*)(rp + 4);
            float2 e2 = *(const float2*)(rp + 8);
            float k0 = kk[h][i*3+0], k1 = kk[h][i*3+1], k2 = kk[h][i*3+2];
            cv0 += k0*a   + k1*m.x + k2*m.y;
            cv1 += k0*m.x + k1*m.y + k2*m.z;
            cv2 += k0*m.y + k1*m.z + k2*m.w;
            cv3 += k0*m.z + k1*m.w + k2*e2.x;
        }
        unsigned long long cl = pack_f32x2(cv0, cv1);
        unsigned long long ch = pack_f32x2(cv2, cv3);
        #pragma unroll
        for (int g = 0; g < 8; g++) {
            unsigned long long w2 = wm2[g][h];
            accl[g] = fma_f32x2(w2, cl, accl[g]);
            acch[g] = fma_f32x2(w2, ch, acch[g]);
        }
    }

    const float m0 = (sq + 0 <= l) ? 1.f : 0.f;
    const float m1 = (sq + 1 <= l) ? 1.f : 0.f;
    const float m2 = (sq + 2 <= l) ? 1.f : 0.f;
    const float m3 = (sq + 3 <= l) ? 1.f : 0.f;

    __half* outb = g_h2 + (size_t)b * 8 * PLANE + (size_t)l * 1024 + sq;
    float es[8];
    #pragma unroll
    for (int g = 0; g < 8; g++) {
        float a0, a1, a2, a3;
        unpack_f32x2(a0, a1, accl[g]);
        unpack_f32x2(a2, a3, acch[g]);
        // MASKED exponentials: Ehat is zero above the causal diagonal.
        float e0 = m0 * __expf(a0);
        float e1 = m1 * __expf(a1);
        float e2v = m2 * __expf(a2);
        float e3 = m3 * __expf(a3);
        sth4(&outb[(size_t)g * PLANE], make_float4(e0, e1, e2v, e3));
        es[g] = e0 + e1 + e2v + e3;
        #pragma unroll
        for (int o = 1; o < 8; o <<= 1)
            es[g] += __shfl_xor_sync(0xffffffffu, es[g], o);
    }
    const int u = tid & 7;
    float val = es[0];
    val = (u == 1) ? es[1] : val;
    val = (u == 2) ? es[2] : val;
    val = (u == 3) ? es[3] : val;
    val = (u == 4) ? es[4] : val;
    val = (u == 5) ? es[5] : val;
    val = (u == 6) ? es[6] : val;
    val = (u == 7) ? es[7] : val;
    g_part[(((size_t)(b * 8 + u) << 10) + l) * 32 + blockIdx.x] = val;
}

// ---------------------------------------------------------------------------
__global__ void __launch_bounds__(256) invz_kernel()
{
    const int row = blockIdx.x * 256 + threadIdx.x;
    const float* p = g_part + (size_t)row * 32;
    float s = 0.f;
    #pragma unroll
    for (int i = 0; i < 8; i++) {
        float4 v = *(const float4*)&p[i << 2];
        s += v.x + v.y + v.z + v.w;
    }
    g_invz[row] = 1.0f / s;
}

// ---------------------------------------------------------------------------
// Pass D: split per head-pair; stages A = Ehat*invZ (Ehat pre-masked -> no
// predicates); conv3x3_after + 2x2 head mix + causal zero. Writes A2 fp16.
// grid (32,32,16): z = b*4+gp. block 256.
// ---------------------------------------------------------------------------
__global__ void __launch_bounds__(256) convhead_kernel(const float* __restrict__ mta_after,
                                                       const float* __restrict__ head_k)
{
    if (blockIdx.x > blockIdx.y) return;
    const int st = blockIdx.x << 5, lt = blockIdx.y << 5;
    const int b  = blockIdx.z >> 2, gp = blockIdx.z & 3;
    const int tid = threadIdx.x;

    __shared__ __align__(16) float sm[2][34][40];
    __shared__ float kk[2][9];
    __shared__ float hk[4];
    if (tid < 18) kk[tid / 9][tid % 9] = mta_after[18 * gp + tid];
    if (tid >= 32 && tid < 36) hk[tid - 32] = head_k[gp * 4 + (tid - 32)];

    const __half* inb = g_h2 + (size_t)(b * 8 + 2 * gp) * PLANE;
    for (int idx = tid; idx < 2 * 34 * 10; idx += 256) {
        int h   = idx / 340;
        int rem = idx - h * 340;
        int r   = rem / 10;
        int c4  = rem - r * 10;
        int gl  = lt - 2 + r;
        int gs  = st - 4 + (c4 << 2);
        float4 v = make_float4(0.f, 0.f, 0.f, 0.f);
        if (gl >= 0 && gs >= 0 && gs <= 1020) {
            float4 e = ldh4(&inb[(size_t)h * PLANE + (size_t)gl * 1024 + gs]);
            float iz = g_invz[(((size_t)(b * 8 + 2 * gp + h)) << 10) + gl];
            v = make_float4(e.x * iz, e.y * iz, e.z * iz, e.w * iz);
        }
        *(float4*)&sm[h][r][c4 << 2] = v;
    }
    __syncthreads();

    const int li = tid >> 3;
    const int c0 = (tid & 7) << 2;
    const int l  = lt + li;
    const int sq = st + c0;
    const float cz0 = (sq + 0 <= l) ? 1.f : 0.f;
    const float cz1 = (sq + 1 <= l) ? 1.f : 0.f;
    const float cz2 = (sq + 2 <= l) ? 1.f : 0.f;
    const float cz3 = (sq + 3 <= l) ? 1.f : 0.f;

    float c0v[4] = {0.f, 0.f, 0.f, 0.f};
    float c1v[4] = {0.f, 0.f, 0.f, 0.f};
    #pragma unroll
    for (int hh = 0; hh < 2; hh++) {
        float* cv = hh ? c1v : c0v;
        #pragma unroll
        for (int i = 0; i < 3; i++) {
            const float* rp = &sm[hh][li + i][c0];
            float  a  = rp[3];
            float4 m  = *(const float4*)(rp + 4);
            float2 e2 = *(const float2*)(rp + 8);
            float k0 = kk[hh][i*3+0], k1 = kk[hh][i*3+1], k2 = kk[hh][i*3+2];
            cv[0] += k0*a   + k1*m.x + k2*m.y;
            cv[1] += k0*m.x + k1*m.y + k2*m.z;
            cv[2] += k0*m.y + k1*m.z + k2*m.w;
            cv[3] += k0*m.z + k1*m.w + k2*e2.x;
        }
    }
    float h00 = hk[0], h01 = hk[1], h10 = hk[2], h11 = hk[3];
    __half* outb = g_h1 + (size_t)(b * 8 + 2 * gp) * PLANE + (size_t)l * 1024 + sq;
    sth4(&outb[0],
         make_float4((c0v[0]*h00 + c1v[0]*h10) * cz0,
                     (c0v[1]*h00 + c1v[1]*h10) * cz1,
                     (c0v[2]*h00 + c1v[2]*h10) * cz2,
                     (c0v[3]*h00 + c1v[3]*h10) * cz3));
    sth4(&outb[PLANE],
         make_float4((c0v[0]*h01 + c1v[0]*h11) * cz0,
                     (c0v[1]*h01 + c1v[1]*h11) * cz1,
                     (c0v[2]*h01 + c1v[2]*h11) * cz2,
                     (c0v[3]*h01 + c1v[3]*h11) * cz3));
}

// ---------------------------------------------------------------------------
// Pass E: out = A2 @ V via fp16 HMMA, PAIRED for load balance (two 128-thread
// sub-blocks on named barriers; tiles t and 31-t per block -> uniform cost).
// A2 above-diagonal is zero, so the overshooting diagonal s-tile is safe.
// grid (32, 16): x = bh, y = pair p. block 256.
// ---------------------------------------------------------------------------
#define AV_AST 72
__global__ void __launch_bounds__(256) av_kernel(const float* __restrict__ v,
                                                 float* __restrict__ out)
{
    const int bh = blockIdx.x;
    const int b  = bh >> 3, h = bh & 7;
    const int p  = blockIdx.y;
    const int tid = threadIdx.x;
    const int half = tid >> 7;
    const int st   = tid & 127;
    const int t    = half ? (31 - p) : p;
    const int l0   = t << 5;
    const int wrp = st >> 5, lane = st & 31;
    const int gid = lane >> 2, tg = lane & 3;
    const int m0  = (wrp & 1) << 4;
    const int n0  = (wrp >> 1) << 5;
    const int bar = 1 + half;

    __shared__ __align__(16) __half  As[2][32][AV_AST];
    __shared__ __align__(16) __half2 Vp[2][64][33];
    const __half* Ab = g_h1 + (size_t)bh * PLANE;
    const float*  vb = v + (size_t)b * L_ * 512 + h * 64;

    float acc[4][4];
    #pragma unroll
    for (int j = 0; j < 4; j++)
        #pragma unroll
        for (int i = 0; i < 4; i++) acc[j][i] = 0.f;

    const int n_iter = (l0 >> 6) + 1;
    for (int it = 0; it < n_iter; it++) {
        const int s0 = it << 6;
        #pragma unroll
        for (int i = 0; i < 4; i++) {
            int idx = st + (i << 7);
            int row = idx >> 4;
            int c   = (idx & 15) << 2;
            *(uint2*)&As[half][row][c] =
                *(const uint2*)&Ab[(size_t)(l0 + row) * 1024 + s0 + c];
        }
        #pragma unroll
        for (int i = 0; i < 4; i++) {
            int idx = st + (i << 7);
            int s2  = idx >> 4;
            int e   = (idx & 15) << 2;
            float4 va = *(const float4*)&vb[(size_t)(s0 + 2 * s2) * 512 + e];
            float4 vc = *(const float4*)&vb[(size_t)(s0 + 2 * s2 + 1) * 512 + e];
            Vp[half][e + 0][s2] = __floats2half2_rn(va.x, vc.x);
            Vp[half][e + 1][s2] = __floats2half2_rn(va.y, vc.y);
            Vp[half][e + 2][s2] = __floats2half2_rn(va.z, vc.z);
            Vp[half][e + 3][s2] = __floats2half2_rn(va.w, vc.w);
        }
        BAR_SYNC_HALF(bar);

        #pragma unroll
        for (int k0 = 0; k0 < 64; k0 += 16) {
            uint32_t a0 = *(const uint32_t*)&As[half][m0 + gid][k0 + 2 * tg];
            uint32_t a1 = *(const uint32_t*)&As[half][m0 + gid + 8][k0 + 2 * tg];
            uint32_t a2 = *(const uint32_t*)&As[half][m0 + gid][k0 + 2 * tg + 8];
            uint32_t a3 = *(const uint32_t*)&As[half][m0 + gid + 8][k0 + 2 * tg + 8];
            int sp = k0 >> 1;
            #pragma unroll
            for (int j = 0; j < 4; j++) {
                int nb = n0 + (j << 3);
                uint32_t b0 = *(const uint32_t*)&Vp[half][nb + gid][sp + tg];
                uint32_t b1 = *(const uint32_t*)&Vp[half][nb + gid][sp + tg + 4];
                mma_f16(acc[j], a0, a1, a2, a3, b0, b1);
            }
        }
        BAR_SYNC_HALF(bar);
    }

    #pragma unroll
    for (int j = 0; j < 4; j++) {
        int e  = n0 + (j << 3) + (tg << 1);
        int l1 = l0 + m0 + gid;
        int l2 = l1 + 8;
        *(float2*)&out[((size_t)(b * L_ + l1) * H_ + h) * 64 + e] =
            make_float2(acc[j][0], acc[j][1]);
        *(float2*)&out[((size_t)(b * L_ + l2) * H_ + h) * 64 + e] =
            make_float2(acc[j][2], acc[j][3]);
    }
}

// ---------------------------------------------------------------------------
extern "C" void kernel_launch(void* const* d_in, const int* in_sizes, int n_in,
                              void* d_out, int out_size)
{
    const float* q         = (const float*)d_in[0];
    const float* k         = (const float*)d_in[1];
    const float* v         = (const float*)d_in[2];
    const float* mta       = (const float*)d_in[3];
    const float* mta_after = (const float*)d_in[4];
    const float* head_k    = (const float*)d_in[5];
    const float* wpsm      = (const float*)d_in[6];
    float* out = (float*)d_out;

    dim3 gA(16, 16, 32);
    qk_kernel<<<gA, 256>>>(q, k);

    dim3 gB(32, 32, 4);
    convmix_kernel<<<gB, 256>>>(mta, wpsm);

    invz_kernel<<<128, 256>>>();

    dim3 gD(32, 32, 16);
    convhead_kernel<<<gD, 256>>>(mta_after, head_k);

    dim3 gE(32, 16);
    av_kernel<<<gE, 256>>>(v, out);
}

// round 16
// speedup vs baseline: 1.0568x; 1.0312x over previous
#include <cuda_runtime.h>
#include <cuda_fp16.h>
#include <cstdint>

#define B_ 4
#define L_ 1024
#define H_ 8
#define PLANE (1024*1024)

// fp16 scratch planes (64 MB each, zero-initialized .bss). Never-written
// regions (strictly-above-diagonal tiles) stay 0x0000 = +0.0h deterministically.
__device__ __half g_h1[(size_t)B_*H_*L_*L_];   // S1, then A2
__device__ __half g_h2[(size_t)B_*H_*L_*L_];   // Ehat = exp(S2), causally masked
__device__ float  g_part[(size_t)B_*H_*L_*32];
__device__ float  g_invz[(size_t)B_*H_*L_];

__device__ __forceinline__ void mma_f16(float c[4],
                                        uint32_t a0, uint32_t a1, uint32_t a2, uint32_t a3,
                                        uint32_t b0, uint32_t b1) {
    asm volatile(
        "mma.sync.aligned.m16n8k16.row.col.f32.f16.f16.f32 "
        "{%0,%1,%2,%3}, {%4,%5,%6,%7}, {%8,%9}, {%0,%1,%2,%3};"
        : "+f"(c[0]), "+f"(c[1]), "+f"(c[2]), "+f"(c[3])
        : "r"(a0), "r"(a1), "r"(a2), "r"(a3), "r"(b0), "r"(b1));
}

__device__ __forceinline__ float4 ldh4(const __half* p) {
    uint2 u = *(const uint2*)p;
    __half2 h0 = *(__half2*)&u.x;
    __half2 h1 = *(__half2*)&u.y;
    float2 f0 = __half22float2(h0);
    float2 f1 = __half22float2(h1);
    return make_float4(f0.x, f0.y, f1.x, f1.y);
}

__device__ __forceinline__ void sth4(__half* p, float4 v) {
    __half2 a = __floats2half2_rn(v.x, v.y);
    __half2 b = __floats2half2_rn(v.z, v.w);
    uint2 u;
    u.x = *(uint32_t*)&a;
    u.y = *(uint32_t*)&b;
    *(uint2*)p = u;
}

__device__ __forceinline__ unsigned long long pack_f32x2(float lo, float hi) {
    unsigned long long r;
    asm("mov.b64 %0, {%1, %2};" : "=l"(r) : "f"(lo), "f"(hi));
    return r;
}
__device__ __forceinline__ void unpack_f32x2(float& lo, float& hi, unsigned long long v) {
    asm("mov.b64 {%0, %1}, %2;" : "=f"(lo), "=f"(hi) : "l"(v));
}
__device__ __forceinline__ unsigned long long fma_f32x2(unsigned long long a,
                                                        unsigned long long b,
                                                        unsigned long long c) {
    unsigned long long r;
    asm("fma.rn.f32x2 %0, %1, %2, %3;" : "=l"(r) : "l"(a), "l"(b), "l"(c));
    return r;
}

#define BAR_SYNC_HALF(id) asm volatile("bar.sync %0, %1;" :: "r"(id), "r"(128) : "memory")

// ---------------------------------------------------------------------------
// Pass A: S1 = (Q.K^T)*scale via fp16 HMMA (fp32 accum); causal zeroed;
// masked tiles skipped. Output fp16. grid (16,16,32), block 256.
// ---------------------------------------------------------------------------
#define QK_ST 72
__global__ void __launch_bounds__(256) qk_kernel(const float* __restrict__ q,
                                                 const float* __restrict__ k)
{
    const int bh = blockIdx.z;
    const int b  = bh >> 3, h = bh & 7;
    const int l0 = blockIdx.y << 6, s0 = blockIdx.x << 6;
    if (s0 > l0 + 63) return;

    const int tid  = threadIdx.x;
    const int wrp  = tid >> 5, lane = tid & 31;
    const int gid  = lane >> 2, tg = lane & 3;
    const int m0   = (wrp & 3) << 4;
    const int n0   = (wrp >> 2) << 5;

    __shared__ __align__(16) __half Qs[64][QK_ST];
    __shared__ __align__(16) __half Ks[64][QK_ST];
    __shared__ __align__(16) float Cs[64][68];
    const float* qb = q + (size_t)b * L_ * 512 + h * 64;
    const float* kb = k + (size_t)b * L_ * 512 + h * 64;

    #pragma unroll
    for (int i = 0; i < 4; i++) {
        int row = (tid >> 4) + (i << 4);
        int c   = (tid & 15) << 2;
        sth4(&Qs[row][c], *(const float4*)&qb[(size_t)(l0 + row) * 512 + c]);
        sth4(&Ks[row][c], *(const float4*)&kb[(size_t)(s0 + row) * 512 + c]);
    }
    __syncthreads();

    float acc[4][4];
    #pragma unroll
    for (int j = 0; j < 4; j++)
        #pragma unroll
        for (int i = 0; i < 4; i++) acc[j][i] = 0.f;

    #pragma unroll
    for (int e0 = 0; e0 < 64; e0 += 16) {
        uint32_t a0 = *(const uint32_t*)&Qs[m0 + gid][e0 + 2 * tg];
        uint32_t a1 = *(const uint32_t*)&Qs[m0 + gid + 8][e0 + 2 * tg];
        uint32_t a2 = *(const uint32_t*)&Qs[m0 + gid][e0 + 2 * tg + 8];
        uint32_t a3 = *(const uint32_t*)&Qs[m0 + gid + 8][e0 + 2 * tg + 8];
        #pragma unroll
        for (int j = 0; j < 4; j++) {
            int nb = n0 + (j << 3);
            uint32_t b0 = *(const uint32_t*)&Ks[nb + gid][e0 + 2 * tg];
            uint32_t b1 = *(const uint32_t*)&Ks[nb + gid][e0 + 2 * tg + 8];
            mma_f16(acc[j], a0, a1, a2, a3, b0, b1);
        }
    }
    __syncthreads();

    #pragma unroll
    for (int j = 0; j < 4; j++) {
        int nb = n0 + (j << 3) + (tg << 1);
        Cs[m0 + gid][nb]         = acc[j][0];
        Cs[m0 + gid][nb + 1]     = acc[j][1];
        Cs[m0 + gid + 8][nb]     = acc[j][2];
        Cs[m0 + gid + 8][nb + 1] = acc[j][3];
    }
    __syncthreads();

    __half* outp = g_h1 + (size_t)bh * PLANE;
    const float scale = 0.125f;
    #pragma unroll
    for (int i = 0; i < 4; i++) {
        int row = (tid >> 4) + (i << 4);
        int c   = (tid & 15) << 2;
        int l   = l0 + row, sb = s0 + c;
        float4 v = *(const float4*)&Cs[row][c];
        float4 r;
        r.x = (sb + 0 <= l) ? v.x * scale : 0.f;
        r.y = (sb + 1 <= l) ? v.y * scale : 0.f;
        r.z = (sb + 2 <= l) ? v.z * scale : 0.f;
        r.w = (sb + 3 <= l) ? v.w * scale : 0.f;
        sth4(&outp[(size_t)l * 1024 + sb], r);
    }
}

// ---------------------------------------------------------------------------
// Pass B: S2[b,g] = sum_h wpsm[g,h]*conv3x3(S1[b,h]); writes Ehat = MASKED
// exp(S2) (fp16) and per-row partial sums of exp to g_part.
// RAW fp16 smem staging (21.8 KB, pure copies); half2->float2 cvt at conv
// loads; identical fp32 FMA order -> bit-identical output.
// grid (32,32,4), block 256, quad per thread.
// ---------------------------------------------------------------------------
__global__ void __launch_bounds__(256) convmix_kernel(const float* __restrict__ mta_k,
                                                      const float* __restrict__ wpsm)
{
    if (blockIdx.x > blockIdx.y) return;
    const int st = blockIdx.x << 5, lt = blockIdx.y << 5, b = blockIdx.z;
    const int tid = threadIdx.x;

    __shared__ __align__(16) __half smh[8][34][40];
    __shared__ float kk[8][9];
    __shared__ unsigned long long wm2[8][8];
    if (tid < 72) kk[tid / 9][tid % 9] = mta_k[tid];
    if (tid >= 128 && tid < 192) {
        int t = tid - 128;
        float w = wpsm[t];
        wm2[t >> 3][t & 7] = pack_f32x2(w, w);
    }

    const __half* inb = g_h1 + (size_t)b * 8 * PLANE;
    for (int idx = tid; idx < 8 * 34 * 10; idx += 256) {
        int h   = idx / 340;
        int rem = idx - h * 340;
        int r   = rem / 10;
        int c4  = rem - r * 10;
        int gl  = lt - 2 + r;
        int gs  = st - 4 + (c4 << 2);
        uint2 v = make_uint2(0u, 0u);
        if (gl >= 0 && gs >= 0 && gs <= 1020)
            v = *(const uint2*)&inb[(size_t)h * PLANE + (size_t)gl * 1024 + gs];
        *(uint2*)&smh[h][r][c4 << 2] = v;
    }
    __syncthreads();

    const int li = tid >> 3;
    const int c0 = (tid & 7) << 2;
    const int l  = lt + li;
    const int sq = st + c0;

    unsigned long long accl[8], acch[8];
    #pragma unroll
    for (int g = 0; g < 8; g++) { accl[g] = 0ull; acch[g] = 0ull; }

    #pragma unroll 1
    for (int h = 0; h < 8; h++) {
        float cv0 = 0.f, cv1 = 0.f, cv2 = 0.f, cv3 = 0.f;
        #pragma unroll
        for (int i = 0; i < 3; i++) {
            const __half* rp = &smh[h][li + i][c0];
            uint32_t ua = *(const uint32_t*)(rp + 2);   // halves c0+2, c0+3
            uint2    ub = *(const uint2*)(rp + 4);      // halves c0+4..c0+7
            uint32_t uc = *(const uint32_t*)(rp + 8);   // halves c0+8, c0+9
            float2 f23 = __half22float2(*(__half2*)&ua);
            float2 f45 = __half22float2(*(__half2*)&ub.x);
            float2 f67 = __half22float2(*(__half2*)&ub.y);
            float2 f89 = __half22float2(*(__half2*)&uc);
            float k0 = kk[h][i*3+0], k1 = kk[h][i*3+1], k2 = kk[h][i*3+2];
            cv0 += k0*f23.y + k1*f45.x + k2*f45.y;
            cv1 += k0*f45.x + k1*f45.y + k2*f67.x;
            cv2 += k0*f45.y + k1*f67.x + k2*f67.y;
            cv3 += k0*f67.x + k1*f67.y + k2*f89.x;
        }
        unsigned long long cl = pack_f32x2(cv0, cv1);
        unsigned long long ch = pack_f32x2(cv2, cv3);
        #pragma unroll
        for (int g = 0; g < 8; g++) {
            unsigned long long w2 = wm2[g][h];
            accl[g] = fma_f32x2(w2, cl, accl[g]);
            acch[g] = fma_f32x2(w2, ch, acch[g]);
        }
    }

    const float m0 = (sq + 0 <= l) ? 1.f : 0.f;
    const float m1 = (sq + 1 <= l) ? 1.f : 0.f;
    const float m2 = (sq + 2 <= l) ? 1.f : 0.f;
    const float m3 = (sq + 3 <= l) ? 1.f : 0.f;

    __half* outb = g_h2 + (size_t)b * 8 * PLANE + (size_t)l * 1024 + sq;
    float es[8];
    #pragma unroll
    for (int g = 0; g < 8; g++) {
        float a0, a1, a2, a3;
        unpack_f32x2(a0, a1, accl[g]);
        unpack_f32x2(a2, a3, acch[g]);
        float e0 = m0 * __expf(a0);
        float e1 = m1 * __expf(a1);
        float e2v = m2 * __expf(a2);
        float e3 = m3 * __expf(a3);
        sth4(&outb[(size_t)g * PLANE], make_float4(e0, e1, e2v, e3));
        es[g] = e0 + e1 + e2v + e3;
        #pragma unroll
        for (int o = 1; o < 8; o <<= 1)
            es[g] += __shfl_xor_sync(0xffffffffu, es[g], o);
    }
    const int u = tid & 7;
    float val = es[0];
    val = (u == 1) ? es[1] : val;
    val = (u == 2) ? es[2] : val;
    val = (u == 3) ? es[3] : val;
    val = (u == 4) ? es[4] : val;
    val = (u == 5) ? es[5] : val;
    val = (u == 6) ? es[6] : val;
    val = (u == 7) ? es[7] : val;
    g_part[(((size_t)(b * 8 + u) << 10) + l) * 32 + blockIdx.x] = val;
}

// ---------------------------------------------------------------------------
__global__ void __launch_bounds__(256) invz_kernel()
{
    const int row = blockIdx.x * 256 + threadIdx.x;
    const float* p = g_part + (size_t)row * 32;
    float s = 0.f;
    #pragma unroll
    for (int i = 0; i < 8; i++) {
        float4 v = *(const float4*)&p[i << 2];
        s += v.x + v.y + v.z + v.w;
    }
    g_invz[row] = 1.0f / s;
}

// ---------------------------------------------------------------------------
// Pass D: split per head-pair. RAW fp16 Ehat staging (pre-masked in g_h2) +
// per-row invz factored into the conv (row-partial FMA, exact fp32).
// conv3x3_after + 2x2 head mix + causal zero. Writes A2 fp16.
// grid (32,32,16): z = b*4+gp. block 256.
// ---------------------------------------------------------------------------
__global__ void __launch_bounds__(256) convhead_kernel(const float* __restrict__ mta_after,
                                                       const float* __restrict__ head_k)
{
    if (blockIdx.x > blockIdx.y) return;
    const int st = blockIdx.x << 5, lt = blockIdx.y << 5;
    const int b  = blockIdx.z >> 2, gp = blockIdx.z & 3;
    const int tid = threadIdx.x;

    __shared__ __align__(16) __half smh[2][34][40];
    __shared__ float izs[2][34];
    __shared__ float kk[2][9];
    __shared__ float hk[4];
    if (tid < 18) kk[tid / 9][tid % 9] = mta_after[18 * gp + tid];
    if (tid >= 32 && tid < 36) hk[tid - 32] = head_k[gp * 4 + (tid - 32)];
    if (tid >= 64 && tid < 132) {
        int t = tid - 64;
        int h = t / 34, r = t % 34;
        int row = lt - 2 + r;
        izs[h][r] = (row >= 0)
                  ? g_invz[(((size_t)(b * 8 + 2 * gp + h)) << 10) + row] : 0.f;
    }

    const __half* inb = g_h2 + (size_t)(b * 8 + 2 * gp) * PLANE;
    for (int idx = tid; idx < 2 * 34 * 10; idx += 256) {
        int h   = idx / 340;
        int rem = idx - h * 340;
        int r   = rem / 10;
        int c4  = rem - r * 10;
        int gl  = lt - 2 + r;
        int gs  = st - 4 + (c4 << 2);
        uint2 v = make_uint2(0u, 0u);
        if (gl >= 0 && gs >= 0 && gs <= 1020)
            v = *(const uint2*)&inb[(size_t)h * PLANE + (size_t)gl * 1024 + gs];
        *(uint2*)&smh[h][r][c4 << 2] = v;
    }
    __syncthreads();

    const int li = tid >> 3;
    const int c0 = (tid & 7) << 2;
    const int l  = lt + li;
    const int sq = st + c0;
    const float cz0 = (sq + 0 <= l) ? 1.f : 0.f;
    const float cz1 = (sq + 1 <= l) ? 1.f : 0.f;
    const float cz2 = (sq + 2 <= l) ? 1.f : 0.f;
    const float cz3 = (sq + 3 <= l) ? 1.f : 0.f;

    float c0v[4] = {0.f, 0.f, 0.f, 0.f};
    float c1v[4] = {0.f, 0.f, 0.f, 0.f};
    #pragma unroll
    for (int hh = 0; hh < 2; hh++) {
        float* cv = hh ? c1v : c0v;
        #pragma unroll
        for (int i = 0; i < 3; i++) {
            const __half* rp = &smh[hh][li + i][c0];
            uint32_t ua = *(const uint32_t*)(rp + 2);
            uint2    ub = *(const uint2*)(rp + 4);
            uint32_t uc = *(const uint32_t*)(rp + 8);
            float2 f23 = __half22float2(*(__half2*)&ua);
            float2 f45 = __half22float2(*(__half2*)&ub.x);
            float2 f67 = __half22float2(*(__half2*)&ub.y);
            float2 f89 = __half22float2(*(__half2*)&uc);
            float k0 = kk[hh][i*3+0], k1 = kk[hh][i*3+1], k2 = kk[hh][i*3+2];
            float izr = izs[hh][li + i];
            float p0 = k0*f23.y + k1*f45.x + k2*f45.y;
            float p1 = k0*f45.x + k1*f45.y + k2*f67.x;
            float p2 = k0*f45.y + k1*f67.x + k2*f67.y;
            float p3 = k0*f67.x + k1*f67.y + k2*f89.x;
            cv[0] = fmaf(izr, p0, cv[0]);
            cv[1] = fmaf(izr, p1, cv[1]);
            cv[2] = fmaf(izr, p2, cv[2]);
            cv[3] = fmaf(izr, p3, cv[3]);
        }
    }
    float h00 = hk[0], h01 = hk[1], h10 = hk[2], h11 = hk[3];
    __half* outb = g_h1 + (size_t)(b * 8 + 2 * gp) * PLANE + (size_t)l * 1024 + sq;
    sth4(&outb[0],
         make_float4((c0v[0]*h00 + c1v[0]*h10) * cz0,
                     (c0v[1]*h00 + c1v[1]*h10) * cz1,
                     (c0v[2]*h00 + c1v[2]*h10) * cz2,
                     (c0v[3]*h00 + c1v[3]*h10) * cz3));
    sth4(&outb[PLANE],
         make_float4((c0v[0]*h01 + c1v[0]*h11) * cz0,
                     (c0v[1]*h01 + c1v[1]*h11) * cz1,
                     (c0v[2]*h01 + c1v[2]*h11) * cz2,
                     (c0v[3]*h01 + c1v[3]*h11) * cz3));
}

// ---------------------------------------------------------------------------
// Pass E: out = A2 @ V via fp16 HMMA, PAIRED for load balance (two 128-thread
// sub-blocks on named barriers; tiles t and 31-t per block -> uniform cost).
// A2 above-diagonal is zero, so the overshooting diagonal s-tile is safe.
// grid (32, 16): x = bh, y = pair p. block 256.
// ---------------------------------------------------------------------------
#define AV_AST 72
__global__ void __launch_bounds__(256) av_kernel(const float* __restrict__ v,
                                                 float* __restrict__ out)
{
    const int bh = blockIdx.x;
    const int b  = bh >> 3, h = bh & 7;
    const int p  = blockIdx.y;
    const int tid = threadIdx.x;
    const int half = tid >> 7;
    const int st   = tid & 127;
    const int t    = half ? (31 - p) : p;
    const int l0   = t << 5;
    const int wrp = st >> 5, lane = st & 31;
    const int gid = lane >> 2, tg = lane & 3;
    const int m0  = (wrp & 1) << 4;
    const int n0  = (wrp >> 1) << 5;
    const int bar = 1 + half;

    __shared__ __align__(16) __half  As[2][32][AV_AST];
    __shared__ __align__(16) __half2 Vp[2][64][33];
    const __half* Ab = g_h1 + (size_t)bh * PLANE;
    const float*  vb = v + (size_t)b * L_ * 512 + h * 64;

    float acc[4][4];
    #pragma unroll
    for (int j = 0; j < 4; j++)
        #pragma unroll
        for (int i = 0; i < 4; i++) acc[j][i] = 0.f;

    const int n_iter = (l0 >> 6) + 1;
    for (int it = 0; it < n_iter; it++) {
        const int s0 = it << 6;
        #pragma unroll
        for (int i = 0; i < 4; i++) {
            int idx = st + (i << 7);
            int row = idx >> 4;
            int c   = (idx & 15) << 2;
            *(uint2*)&As[half][row][c] =
                *(const uint2*)&Ab[(size_t)(l0 + row) * 1024 + s0 + c];
        }
        #pragma unroll
        for (int i = 0; i < 4; i++) {
            int idx = st + (i << 7);
            int s2  = idx >> 4;
            int e   = (idx & 15) << 2;
            float4 va = *(const float4*)&vb[(size_t)(s0 + 2 * s2) * 512 + e];
            float4 vc = *(const float4*)&vb[(size_t)(s0 + 2 * s2 + 1) * 512 + e];
            Vp[half][e + 0][s2] = __floats2half2_rn(va.x, vc.x);
            Vp[half][e + 1][s2] = __floats2half2_rn(va.y, vc.y);
            Vp[half][e + 2][s2] = __floats2half2_rn(va.z, vc.z);
            Vp[half][e + 3][s2] = __floats2half2_rn(va.w, vc.w);
        }
        BAR_SYNC_HALF(bar);

        #pragma unroll
        for (int k0 = 0; k0 < 64; k0 += 16) {
            uint32_t a0 = *(const uint32_t*)&As[half][m0 + gid][k0 + 2 * tg];
            uint32_t a1 = *(const uint32_t*)&As[half][m0 + gid + 8][k0 + 2 * tg];
            uint32_t a2 = *(const uint32_t*)&As[half][m0 + gid][k0 + 2 * tg + 8];
            uint32_t a3 = *(const uint32_t*)&As[half][m0 + gid + 8][k0 + 2 * tg + 8];
            int sp = k0 >> 1;
            #pragma unroll
            for (int j = 0; j < 4; j++) {
                int nb = n0 + (j << 3);
                uint32_t b0 = *(const uint32_t*)&Vp[half][nb + gid][sp + tg];
                uint32_t b1 = *(const uint32_t*)&Vp[half][nb + gid][sp + tg + 4];
                mma_f16(acc[j], a0, a1, a2, a3, b0, b1);
            }
        }
        BAR_SYNC_HALF(bar);
    }

    #pragma unroll
    for (int j = 0; j < 4; j++) {
        int e  = n0 + (j << 3) + (tg << 1);
        int l1 = l0 + m0 + gid;
        int l2 = l1 + 8;
        *(float2*)&out[((size_t)(b * L_ + l1) * H_ + h) * 64 + e] =
            make_float2(acc[j][0], acc[j][1]);
        *(float2*)&out[((size_t)(b * L_ + l2) * H_ + h) * 64 + e] =
            make_float2(acc[j][2], acc[j][3]);
    }
}

// ---------------------------------------------------------------------------
extern "C" void kernel_launch(void* const* d_in, const int* in_sizes, int n_in,
                              void* d_out, int out_size)
{
    const float* q         = (const float*)d_in[0];
    const float* k         = (const float*)d_in[1];
    const float* v         = (const float*)d_in[2];
    const float* mta       = (const float*)d_in[3];
    const float* mta_after = (const float*)d_in[4];
    const float* head_k    = (const float*)d_in[5];
    const float* wpsm      = (const float*)d_in[6];
    float* out = (float*)d_out;

    dim3 gA(16, 16, 32);
    qk_kernel<<<gA, 256>>>(q, k);

    dim3 gB(32, 32, 4);
    convmix_kernel<<<gB, 256>>>(mta, wpsm);

    invz_kernel<<<128, 256>>>();

    dim3 gD(32, 32, 16);
    convhead_kernel<<<gD, 256>>>(mta_after, head_k);

    dim3 gE(32, 16);
    av_kernel<<<gE, 256>>>(v, out);
}

// round 17
// speedup vs baseline: 1.1183x; 1.0582x over previous
#include <cuda_runtime.h>
#include <cuda_fp16.h>
#include <cstdint>

#define B_ 4
#define L_ 1024
#define H_ 8
#define PLANE (1024*1024)

// fp16 scratch planes (64 MB each, zero-initialized .bss). Never-written
// regions (strictly-above-diagonal tiles) stay 0x0000 = +0.0h deterministically.
__device__ __half g_h1[(size_t)B_*H_*L_*L_];   // S1, then A2
__device__ __half g_h2[(size_t)B_*H_*L_*L_];   // Ehat = exp(S2), causally masked
__device__ float  g_part[(size_t)B_*H_*L_*32];
__device__ float  g_invz[(size_t)B_*H_*L_];

__device__ __forceinline__ void mma_f16(float c[4],
                                        uint32_t a0, uint32_t a1, uint32_t a2, uint32_t a3,
                                        uint32_t b0, uint32_t b1) {
    asm volatile(
        "mma.sync.aligned.m16n8k16.row.col.f32.f16.f16.f32 "
        "{%0,%1,%2,%3}, {%4,%5,%6,%7}, {%8,%9}, {%0,%1,%2,%3};"
        : "+f"(c[0]), "+f"(c[1]), "+f"(c[2]), "+f"(c[3])
        : "r"(a0), "r"(a1), "r"(a2), "r"(a3), "r"(b0), "r"(b1));
}

__device__ __forceinline__ float4 ldh4(const __half* p) {
    uint2 u = *(const uint2*)p;
    __half2 h0 = *(__half2*)&u.x;
    __half2 h1 = *(__half2*)&u.y;
    float2 f0 = __half22float2(h0);
    float2 f1 = __half22float2(h1);
    return make_float4(f0.x, f0.y, f1.x, f1.y);
}

__device__ __forceinline__ void sth4(__half* p, float4 v) {
    __half2 a = __floats2half2_rn(v.x, v.y);
    __half2 b = __floats2half2_rn(v.z, v.w);
    uint2 u;
    u.x = *(uint32_t*)&a;
    u.y = *(uint32_t*)&b;
    *(uint2*)p = u;
}

typedef unsigned long long ull;
__device__ __forceinline__ ull pack_f32x2(float lo, float hi) {
    ull r;
    asm("mov.b64 %0, {%1, %2};" : "=l"(r) : "f"(lo), "f"(hi));
    return r;
}
__device__ __forceinline__ void unpack_f32x2(float& lo, float& hi, ull v) {
    asm("mov.b64 {%0, %1}, %2;" : "=f"(lo), "=f"(hi) : "l"(v));
}
__device__ __forceinline__ ull fma_f32x2(ull a, ull b, ull c) {
    ull r;
    asm("fma.rn.f32x2 %0, %1, %2, %3;" : "=l"(r) : "l"(a), "l"(b), "l"(c));
    return r;
}
// half2 (as uint32) -> f32x2 (as ull)
__device__ __forceinline__ ull h2_to_x2(uint32_t u) {
    float2 f = __half22float2(*(__half2*)&u);
    return pack_f32x2(f.x, f.y);
}

#define BAR_SYNC_HALF(id) asm volatile("bar.sync %0, %1;" :: "r"(id), "r"(128) : "memory")

// ---------------------------------------------------------------------------
// Pass A: S1 = (Q.K^T)*scale via fp16 HMMA (fp32 accum); causal zeroed;
// masked tiles skipped. Output fp16. grid (16,16,32), block 256.
// ---------------------------------------------------------------------------
#define QK_ST 72
__global__ void __launch_bounds__(256) qk_kernel(const float* __restrict__ q,
                                                 const float* __restrict__ k)
{
    const int bh = blockIdx.z;
    const int b  = bh >> 3, h = bh & 7;
    const int l0 = blockIdx.y << 6, s0 = blockIdx.x << 6;
    if (s0 > l0 + 63) return;

    const int tid  = threadIdx.x;
    const int wrp  = tid >> 5, lane = tid & 31;
    const int gid  = lane >> 2, tg = lane & 3;
    const int m0   = (wrp & 3) << 4;
    const int n0   = (wrp >> 2) << 5;

    __shared__ __align__(16) __half Qs[64][QK_ST];
    __shared__ __align__(16) __half Ks[64][QK_ST];
    __shared__ __align__(16) float Cs[64][68];
    const float* qb = q + (size_t)b * L_ * 512 + h * 64;
    const float* kb = k + (size_t)b * L_ * 512 + h * 64;

    #pragma unroll
    for (int i = 0; i < 4; i++) {
        int row = (tid >> 4) + (i << 4);
        int c   = (tid & 15) << 2;
        sth4(&Qs[row][c], *(const float4*)&qb[(size_t)(l0 + row) * 512 + c]);
        sth4(&Ks[row][c], *(const float4*)&kb[(size_t)(s0 + row) * 512 + c]);
    }
    __syncthreads();

    float acc[4][4];
    #pragma unroll
    for (int j = 0; j < 4; j++)
        #pragma unroll
        for (int i = 0; i < 4; i++) acc[j][i] = 0.f;

    #pragma unroll
    for (int e0 = 0; e0 < 64; e0 += 16) {
        uint32_t a0 = *(const uint32_t*)&Qs[m0 + gid][e0 + 2 * tg];
        uint32_t a1 = *(const uint32_t*)&Qs[m0 + gid + 8][e0 + 2 * tg];
        uint32_t a2 = *(const uint32_t*)&Qs[m0 + gid][e0 + 2 * tg + 8];
        uint32_t a3 = *(const uint32_t*)&Qs[m0 + gid + 8][e0 + 2 * tg + 8];
        #pragma unroll
        for (int j = 0; j < 4; j++) {
            int nb = n0 + (j << 3);
            uint32_t b0 = *(const uint32_t*)&Ks[nb + gid][e0 + 2 * tg];
            uint32_t b1 = *(const uint32_t*)&Ks[nb + gid][e0 + 2 * tg + 8];
            mma_f16(acc[j], a0, a1, a2, a3, b0, b1);
        }
    }
    __syncthreads();

    #pragma unroll
    for (int j = 0; j < 4; j++) {
        int nb = n0 + (j << 3) + (tg << 1);
        Cs[m0 + gid][nb]         = acc[j][0];
        Cs[m0 + gid][nb + 1]     = acc[j][1];
        Cs[m0 + gid + 8][nb]     = acc[j][2];
        Cs[m0 + gid + 8][nb + 1] = acc[j][3];
    }
    __syncthreads();

    __half* outp = g_h1 + (size_t)bh * PLANE;
    const float scale = 0.125f;
    #pragma unroll
    for (int i = 0; i < 4; i++) {
        int row = (tid >> 4) + (i << 4);
        int c   = (tid & 15) << 2;
        int l   = l0 + row, sb = s0 + c;
        float4 v = *(const float4*)&Cs[row][c];
        float4 r;
        r.x = (sb + 0 <= l) ? v.x * scale : 0.f;
        r.y = (sb + 1 <= l) ? v.y * scale : 0.f;
        r.z = (sb + 2 <= l) ? v.z * scale : 0.f;
        r.w = (sb + 3 <= l) ? v.w * scale : 0.f;
        sth4(&outp[(size_t)l * 1024 + sb], r);
    }
}

// ---------------------------------------------------------------------------
// Pass B: S2[b,g] = sum_h wpsm[g,h]*conv3x3(S1[b,h]); writes Ehat = MASKED
// exp(S2) (fp16) and per-row partial sums of exp to g_part.
// Head-PAIR interleaved smem: smp[pp][r][c] = half2{S1_h, S1_h+1}; one LDS
// serves both heads; conv in packed f32x2 with per-head tap pairs.
// grid (32,32,4), block 256, quad per thread.
// ---------------------------------------------------------------------------
__global__ void __launch_bounds__(256) convmix_kernel(const float* __restrict__ mta_k,
                                                      const float* __restrict__ wpsm)
{
    if (blockIdx.x > blockIdx.y) return;
    const int st = blockIdx.x << 5, lt = blockIdx.y << 5, b = blockIdx.z;
    const int tid = threadIdx.x;

    __shared__ __align__(16) uint32_t smp[4][34][40];
    __shared__ ull kk2[4][9];        // f32x2 taps {h=2pp, h=2pp+1}
    __shared__ ull wm2[8][8];        // dual-lane broadcast of wpsm (pixel pairs)
    if (tid < 36) {
        int pp = tid / 9, j = tid % 9;
        kk2[pp][j] = pack_f32x2(mta_k[(2 * pp) * 9 + j], mta_k[(2 * pp + 1) * 9 + j]);
    }
    if (tid >= 128 && tid < 192) {
        int t = tid - 128;
        float w = wpsm[t];
        wm2[t >> 3][t & 7] = pack_f32x2(w, w);
    }

    const __half* inb = g_h1 + (size_t)b * 8 * PLANE;
    for (int idx = tid; idx < 4 * 34 * 10; idx += 256) {
        int pp  = idx / 340;
        int rem = idx - pp * 340;
        int r   = rem / 10;
        int c4  = rem - r * 10;
        int gl  = lt - 2 + r;
        int gs  = st - 4 + (c4 << 2);
        uint2 v0 = make_uint2(0u, 0u), v1 = make_uint2(0u, 0u);
        if (gl >= 0 && gs >= 0 && gs <= 1020) {
            const __half* p0 = inb + (size_t)(2 * pp) * PLANE + (size_t)gl * 1024 + gs;
            v0 = *(const uint2*)p0;
            v1 = *(const uint2*)(p0 + PLANE);
        }
        __half2 a01 = *(__half2*)&v0.x, a23 = *(__half2*)&v0.y;
        __half2 b01 = *(__half2*)&v1.x, b23 = *(__half2*)&v1.y;
        uint4 o;
        *(__half2*)&o.x = __lows2half2(a01, b01);
        *(__half2*)&o.y = __highs2half2(a01, b01);
        *(__half2*)&o.z = __lows2half2(a23, b23);
        *(__half2*)&o.w = __highs2half2(a23, b23);
        *(uint4*)&smp[pp][r][c4 << 2] = o;
    }
    __syncthreads();

    const int li = tid >> 3;
    const int c0 = (tid & 7) << 2;
    const int l  = lt + li;
    const int sq = st + c0;

    ull accl[8], acch[8];            // f32x2 over pixel pairs (0,1) / (2,3)
    #pragma unroll
    for (int g = 0; g < 8; g++) { accl[g] = 0ull; acch[g] = 0ull; }

    #pragma unroll 1
    for (int pp = 0; pp < 4; pp++) {
        ull pcv0 = 0ull, pcv1 = 0ull, pcv2 = 0ull, pcv3 = 0ull;  // lanes = heads
        #pragma unroll
        for (int i = 0; i < 3; i++) {
            const uint32_t* rp = &smp[pp][li + i][c0];
            uint32_t u0 = rp[3];
            uint4    um = *(const uint4*)(rp + 4);
            uint32_t u5 = rp[8];
            ull W0 = h2_to_x2(u0);
            ull W1 = h2_to_x2(um.x);
            ull W2 = h2_to_x2(um.y);
            ull W3 = h2_to_x2(um.z);
            ull W4 = h2_to_x2(um.w);
            ull W5 = h2_to_x2(u5);
            ull K0 = kk2[pp][i*3+0], K1 = kk2[pp][i*3+1], K2 = kk2[pp][i*3+2];
            pcv0 = fma_f32x2(K0, W0, fma_f32x2(K1, W1, fma_f32x2(K2, W2, pcv0)));
            pcv1 = fma_f32x2(K0, W1, fma_f32x2(K1, W2, fma_f32x2(K2, W3, pcv1)));
            pcv2 = fma_f32x2(K0, W2, fma_f32x2(K1, W3, fma_f32x2(K2, W4, pcv2)));
            pcv3 = fma_f32x2(K0, W3, fma_f32x2(K1, W4, fma_f32x2(K2, W5, pcv3)));
        }
        // split heads, repack over pixel pairs
        float p0a, p0b, p1a, p1b, p2a, p2b, p3a, p3b;
        unpack_f32x2(p0a, p0b, pcv0);
        unpack_f32x2(p1a, p1b, pcv1);
        unpack_f32x2(p2a, p2b, pcv2);
        unpack_f32x2(p3a, p3b, pcv3);
        ull cl0 = pack_f32x2(p0a, p1a), ch0 = pack_f32x2(p2a, p3a);  // head 2pp
        ull cl1 = pack_f32x2(p0b, p1b), ch1 = pack_f32x2(p2b, p3b);  // head 2pp+1
        #pragma unroll
        for (int g = 0; g < 8; g++) {
            ull wa = wm2[g][2 * pp];
            ull wb = wm2[g][2 * pp + 1];
            accl[g] = fma_f32x2(wa, cl0, accl[g]);
            accl[g] = fma_f32x2(wb, cl1, accl[g]);
            acch[g] = fma_f32x2(wa, ch0, acch[g]);
            acch[g] = fma_f32x2(wb, ch1, acch[g]);
        }
    }

    const float m0 = (sq + 0 <= l) ? 1.f : 0.f;
    const float m1 = (sq + 1 <= l) ? 1.f : 0.f;
    const float m2 = (sq + 2 <= l) ? 1.f : 0.f;
    const float m3 = (sq + 3 <= l) ? 1.f : 0.f;

    __half* outb = g_h2 + (size_t)b * 8 * PLANE + (size_t)l * 1024 + sq;
    float es[8];
    #pragma unroll
    for (int g = 0; g < 8; g++) {
        float a0, a1, a2, a3;
        unpack_f32x2(a0, a1, accl[g]);
        unpack_f32x2(a2, a3, acch[g]);
        float e0 = m0 * __expf(a0);
        float e1 = m1 * __expf(a1);
        float e2v = m2 * __expf(a2);
        float e3 = m3 * __expf(a3);
        sth4(&outb[(size_t)g * PLANE], make_float4(e0, e1, e2v, e3));
        es[g] = e0 + e1 + e2v + e3;
        #pragma unroll
        for (int o = 1; o < 8; o <<= 1)
            es[g] += __shfl_xor_sync(0xffffffffu, es[g], o);
    }
    const int u = tid & 7;
    float val = es[0];
    val = (u == 1) ? es[1] : val;
    val = (u == 2) ? es[2] : val;
    val = (u == 3) ? es[3] : val;
    val = (u == 4) ? es[4] : val;
    val = (u == 5) ? es[5] : val;
    val = (u == 6) ? es[6] : val;
    val = (u == 7) ? es[7] : val;
    g_part[(((size_t)(b * 8 + u) << 10) + l) * 32 + blockIdx.x] = val;
}

// ---------------------------------------------------------------------------
__global__ void __launch_bounds__(256) invz_kernel()
{
    const int row = blockIdx.x * 256 + threadIdx.x;
    const float* p = g_part + (size_t)row * 32;
    float s = 0.f;
    #pragma unroll
    for (int i = 0; i < 8; i++) {
        float4 v = *(const float4*)&p[i << 2];
        s += v.x + v.y + v.z + v.w;
    }
    g_invz[row] = 1.0f / s;
}

// ---------------------------------------------------------------------------
// Pass D: split per head-pair. Interleaved {h0,h1} half2 staging of pre-masked
// Ehat; conv + per-row invz in packed f32x2; 2x2 head mix + causal zero.
// Writes A2 fp16. grid (32,32,16): z = b*4+gp. block 256.
// ---------------------------------------------------------------------------
__global__ void __launch_bounds__(256) convhead_kernel(const float* __restrict__ mta_after,
                                                       const float* __restrict__ head_k)
{
    if (blockIdx.x > blockIdx.y) return;
    const int st = blockIdx.x << 5, lt = blockIdx.y << 5;
    const int b  = blockIdx.z >> 2, gp = blockIdx.z & 3;
    const int tid = threadIdx.x;

    __shared__ __align__(16) uint32_t smp[34][40];
    __shared__ ull izs2[34];     // f32x2 {invz_h0[row], invz_h1[row]}
    __shared__ ull kk2[9];       // f32x2 taps {h0, h1}
    __shared__ float hk[4];
    if (tid < 9) kk2[tid] = pack_f32x2(mta_after[18 * gp + tid],
                                       mta_after[18 * gp + 9 + tid]);
    if (tid >= 32 && tid < 36) hk[tid - 32] = head_k[gp * 4 + (tid - 32)];
    if (tid >= 64 && tid < 98) {
        int r = tid - 64;
        int row = lt - 2 + r;
        float i0 = 0.f, i1 = 0.f;
        if (row >= 0) {
            i0 = g_invz[(((size_t)(b * 8 + 2 * gp)) << 10) + row];
            i1 = g_invz[(((size_t)(b * 8 + 2 * gp + 1)) << 10) + row];
        }
        izs2[r] = pack_f32x2(i0, i1);
    }

    const __half* inb = g_h2 + (size_t)(b * 8 + 2 * gp) * PLANE;
    for (int idx = tid; idx < 34 * 10; idx += 256) {
        int r   = idx / 10;
        int c4  = idx - r * 10;
        int gl  = lt - 2 + r;
        int gs  = st - 4 + (c4 << 2);
        uint2 v0 = make_uint2(0u, 0u), v1 = make_uint2(0u, 0u);
        if (gl >= 0 && gs >= 0 && gs <= 1020) {
            const __half* p0 = inb + (size_t)gl * 1024 + gs;
            v0 = *(const uint2*)p0;
            v1 = *(const uint2*)(p0 + PLANE);
        }
        __half2 a01 = *(__half2*)&v0.x, a23 = *(__half2*)&v0.y;
        __half2 b01 = *(__half2*)&v1.x, b23 = *(__half2*)&v1.y;
        uint4 o;
        *(__half2*)&o.x = __lows2half2(a01, b01);
        *(__half2*)&o.y = __highs2half2(a01, b01);
        *(__half2*)&o.z = __lows2half2(a23, b23);
        *(__half2*)&o.w = __highs2half2(a23, b23);
        *(uint4*)&smp[r][c4 << 2] = o;
    }
    __syncthreads();

    const int li = tid >> 3;
    const int c0 = (tid & 7) << 2;
    const int l  = lt + li;
    const int sq = st + c0;
    const float cz0 = (sq + 0 <= l) ? 1.f : 0.f;
    const float cz1 = (sq + 1 <= l) ? 1.f : 0.f;
    const float cz2 = (sq + 2 <= l) ? 1.f : 0.f;
    const float cz3 = (sq + 3 <= l) ? 1.f : 0.f;

    ull pcv0 = 0ull, pcv1 = 0ull, pcv2 = 0ull, pcv3 = 0ull;  // lanes = heads
    #pragma unroll
    for (int i = 0; i < 3; i++) {
        const uint32_t* rp = &smp[li + i][c0];
        uint32_t u0 = rp[3];
        uint4    um = *(const uint4*)(rp + 4);
        uint32_t u5 = rp[8];
        ull W0 = h2_to_x2(u0);
        ull W1 = h2_to_x2(um.x);
        ull W2 = h2_to_x2(um.y);
        ull W3 = h2_to_x2(um.z);
        ull W4 = h2_to_x2(um.w);
        ull W5 = h2_to_x2(u5);
        ull K0 = kk2[i*3+0], K1 = kk2[i*3+1], K2 = kk2[i*3+2];
        ull IZ = izs2[li + i];
        ull p0 = fma_f32x2(K0, W0, fma_f32x2(K1, W1, fma_f32x2(K2, W2, 0ull)));
        ull p1 = fma_f32x2(K0, W1, fma_f32x2(K1, W2, fma_f32x2(K2, W3, 0ull)));
        ull p2 = fma_f32x2(K0, W2, fma_f32x2(K1, W3, fma_f32x2(K2, W4, 0ull)));
        ull p3 = fma_f32x2(K0, W3, fma_f32x2(K1, W4, fma_f32x2(K2, W5, 0ull)));
        pcv0 = fma_f32x2(IZ, p0, pcv0);
        pcv1 = fma_f32x2(IZ, p1, pcv1);
        pcv2 = fma_f32x2(IZ, p2, pcv2);
        pcv3 = fma_f32x2(IZ, p3, pcv3);
    }
    float c0v[4], c1v[4];
    unpack_f32x2(c0v[0], c1v[0], pcv0);
    unpack_f32x2(c0v[1], c1v[1], pcv1);
    unpack_f32x2(c0v[2], c1v[2], pcv2);
    unpack_f32x2(c0v[3], c1v[3], pcv3);

    float h00 = hk[0], h01 = hk[1], h10 = hk[2], h11 = hk[3];
    __half* outb = g_h1 + (size_t)(b * 8 + 2 * gp) * PLANE + (size_t)l * 1024 + sq;
    sth4(&outb[0],
         make_float4((c0v[0]*h00 + c1v[0]*h10) * cz0,
                     (c0v[1]*h00 + c1v[1]*h10) * cz1,
                     (c0v[2]*h00 + c1v[2]*h10) * cz2,
                     (c0v[3]*h00 + c1v[3]*h10) * cz3));
    sth4(&outb[PLANE],
         make_float4((c0v[0]*h01 + c1v[0]*h11) * cz0,
                     (c0v[1]*h01 + c1v[1]*h11) * cz1,
                     (c0v[2]*h01 + c1v[2]*h11) * cz2,
                     (c0v[3]*h01 + c1v[3]*h11) * cz3));
}

// ---------------------------------------------------------------------------
// Pass E: out = A2 @ V via fp16 HMMA, PAIRED for load balance (two 128-thread
// sub-blocks on named barriers; tiles t and 31-t per block -> uniform cost).
// A2 above-diagonal is zero, so the overshooting diagonal s-tile is safe.
// grid (32, 16): x = bh, y = pair p. block 256.
// ---------------------------------------------------------------------------
#define AV_AST 72
__global__ void __launch_bounds__(256) av_kernel(const float* __restrict__ v,
                                                 float* __restrict__ out)
{
    const int bh = blockIdx.x;
    const int b  = bh >> 3, h = bh & 7;
    const int p  = blockIdx.y;
    const int tid = threadIdx.x;
    const int half = tid >> 7;
    const int st   = tid & 127;
    const int t    = half ? (31 - p) : p;
    const int l0   = t << 5;
    const int wrp = st >> 5, lane = st & 31;
    const int gid = lane >> 2, tg = lane & 3;
    const int m0  = (wrp & 1) << 4;
    const int n0  = (wrp >> 1) << 5;
    const int bar = 1 + half;

    __shared__ __align__(16) __half  As[2][32][AV_AST];
    __shared__ __align__(16) __half2 Vp[2][64][33];
    const __half* Ab = g_h1 + (size_t)bh * PLANE;
    const float*  vb = v + (size_t)b * L_ * 512 + h * 64;

    float acc[4][4];
    #pragma unroll
    for (int j = 0; j < 4; j++)
        #pragma unroll
        for (int i = 0; i < 4; i++) acc[j][i] = 0.f;

    const int n_iter = (l0 >> 6) + 1;
    for (int it = 0; it < n_iter; it++) {
        const int s0 = it << 6;
        #pragma unroll
        for (int i = 0; i < 4; i++) {
            int idx = st + (i << 7);
            int row = idx >> 4;
            int c   = (idx & 15) << 2;
            *(uint2*)&As[half][row][c] =
                *(const uint2*)&Ab[(size_t)(l0 + row) * 1024 + s0 + c];
        }
        #pragma unroll
        for (int i = 0; i < 4; i++) {
            int idx = st + (i << 7);
            int s2  = idx >> 4;
            int e   = (idx & 15) << 2;
            float4 va = *(const float4*)&vb[(size_t)(s0 + 2 * s2) * 512 + e];
            float4 vc = *(const float4*)&vb[(size_t)(s0 + 2 * s2 + 1) * 512 + e];
            Vp[half][e + 0][s2] = __floats2half2_rn(va.x, vc.x);
            Vp[half][e + 1][s2] = __floats2half2_rn(va.y, vc.y);
            Vp[half][e + 2][s2] = __floats2half2_rn(va.z, vc.z);
            Vp[half][e + 3][s2] = __floats2half2_rn(va.w, vc.w);
        }
        BAR_SYNC_HALF(bar);

        #pragma unroll
        for (int k0 = 0; k0 < 64; k0 += 16) {
            uint32_t a0 = *(const uint32_t*)&As[half][m0 + gid][k0 + 2 * tg];
            uint32_t a1 = *(const uint32_t*)&As[half][m0 + gid + 8][k0 + 2 * tg];
            uint32_t a2 = *(const uint32_t*)&As[half][m0 + gid][k0 + 2 * tg + 8];
            uint32_t a3 = *(const uint32_t*)&As[half][m0 + gid + 8][k0 + 2 * tg + 8];
            int sp = k0 >> 1;
            #pragma unroll
            for (int j = 0; j < 4; j++) {
                int nb = n0 + (j << 3);
                uint32_t b0 = *(const uint32_t*)&Vp[half][nb + gid][sp + tg];
                uint32_t b1 = *(const uint32_t*)&Vp[half][nb + gid][sp + tg + 4];
                mma_f16(acc[j], a0, a1, a2, a3, b0, b1);
            }
        }
        BAR_SYNC_HALF(bar);
    }

    #pragma unroll
    for (int j = 0; j < 4; j++) {
        int e  = n0 + (j << 3) + (tg << 1);
        int l1 = l0 + m0 + gid;
        int l2 = l1 + 8;
        *(float2*)&out[((size_t)(b * L_ + l1) * H_ + h) * 64 + e] =
            make_float2(acc[j][0], acc[j][1]);
        *(float2*)&out[((size_t)(b * L_ + l2) * H_ + h) * 64 + e] =
            make_float2(acc[j][2], acc[j][3]);
    }
}

// ---------------------------------------------------------------------------
extern "C" void kernel_launch(void* const* d_in, const int* in_sizes, int n_in,
                              void* d_out, int out_size)
{
    const float* q         = (const float*)d_in[0];
    const float* k         = (const float*)d_in[1];
    const float* v         = (const float*)d_in[2];
    const float* mta       = (const float*)d_in[3];
    const float* mta_after = (const float*)d_in[4];
    const float* head_k    = (const float*)d_in[5];
    const float* wpsm      = (const float*)d_in[6];
    float* out = (float*)d_out;

    dim3 gA(16, 16, 32);
    qk_kernel<<<gA, 256>>>(q, k);

    dim3 gB(32, 32, 4);
    convmix_kernel<<<gB, 256>>>(mta, wpsm);

    invz_kernel<<<128, 256>>>();

    dim3 gD(32, 32, 16);
    convhead_kernel<<<gD, 256>>>(mta_after, head_k);

    dim3 gE(32, 16);
    av_kernel<<<gE, 256>>>(v, out);
}